// round 4
// baseline (speedup 1.0000x reference)
#include <cuda_runtime.h>
#include <math.h>

#define Bc 32
#define Nn 784
#define DIMc 512
#define Hh 8
#define KDc 32
#define VDc 128
#define QKV_OUTc 1536
#define VAL_ATTNc 1024
#define SCALE 0.17677669529663687f

// ---------------- scratch (static device globals) ----------------
__device__ float g_q[Bc * Hh * Nn * KDc];          // [b][h][n][32]
__device__ float g_k[Bc * Hh * Nn * KDc];          // [b][h][n][32]
__device__ float g_v[Bc * Hh * Nn * VDc];          // [b][h][n][128]
__device__ float g_o[Bc * Nn * VAL_ATTNc];         // [b][n][h*128+d]
__device__ float g_bias[Hh * Nn * Nn];             // [h][n][m]
__device__ float g_qs[QKV_OUTc], g_qbb[QKV_OUTc];
__device__ float g_ps[DIMc], g_pbb[DIMc];

// ---------------- f32x2 helpers (FFMA2: 2x fp32 FMA rate on sm_103a) ----------------
static __device__ __forceinline__ unsigned long long pack2(float lo, float hi) {
    unsigned long long r;
    asm("mov.b64 %0, {%1, %2};" : "=l"(r) : "r"(__float_as_uint(lo)), "r"(__float_as_uint(hi)));
    return r;
}
static __device__ __forceinline__ float2 unpack2(unsigned long long v) {
    unsigned int lo, hi;
    asm("mov.b64 {%0, %1}, %2;" : "=r"(lo), "=r"(hi) : "l"(v));
    return make_float2(__uint_as_float(lo), __uint_as_float(hi));
}
static __device__ __forceinline__ void fma2(unsigned long long& d, unsigned long long a, unsigned long long b) {
    asm("fma.rn.f32x2 %0, %1, %2, %0;" : "+l"(d) : "l"(a), "l"(b));
}

// ---------------- BN coefficient folding ----------------
__global__ void bn_coef_kernel(const float* __restrict__ qg, const float* __restrict__ qb,
                               const float* __restrict__ qm, const float* __restrict__ qv,
                               const float* __restrict__ pg, const float* __restrict__ pb,
                               const float* __restrict__ pm, const float* __restrict__ pv) {
    int i = blockIdx.x * 256 + threadIdx.x;
    if (i < QKV_OUTc) {
        float s = qg[i] * rsqrtf(qv[i] + 1e-5f);
        g_qs[i] = s;
        g_qbb[i] = qb[i] - qm[i] * s;
    }
    if (i < DIMc) {
        float s = pg[i] * rsqrtf(pv[i] + 1e-5f);
        g_ps[i] = s;
        g_pbb[i] = pb[i] - pm[i] * s;
    }
}

// ---------------- bias gather: g_bias[h][n][m] = ab[h, idxs[n,m]] ----------------
__global__ void bias_kernel(const float* __restrict__ ab, const int* __restrict__ idxs) {
    int nm = blockIdx.x * 256 + threadIdx.x;
    if (nm < Nn * Nn) {
        int idx = idxs[nm];
#pragma unroll
        for (int h = 0; h < Hh; h++)
            g_bias[h * Nn * Nn + nm] = ab[h * Nn + idx];
    }
}

// ---------------- QKV GEMM: C[m,o] = sum_k x[m,k]*w[o,k], + BN, scatter ----------------
static __device__ __forceinline__ void qkv_scatter(int b, int n, int o, float y) {
    int h = o / 192, r = o - h * 192;
    if (r < KDc)            g_q[((b * Hh + h) * Nn + n) * KDc + r] = y;
    else if (r < 2 * KDc)   g_k[((b * Hh + h) * Nn + n) * KDc + (r - KDc)] = y;
    else                    g_v[((b * Hh + h) * Nn + n) * VDc + (r - 2 * KDc)] = y;
}

__global__ __launch_bounds__(256, 2) void qkv_gemm_kernel(const float* __restrict__ x,
                                                          const float* __restrict__ w) {
    __shared__ float As[16][136];   // [k][row], padded
    __shared__ float Bs[16][136];
    int m0 = blockIdx.x * 128, o0 = blockIdx.y * 128;
    int t = threadIdx.x, tx = t & 15, ty = t >> 4;

    unsigned long long acc[8][4];
#pragma unroll
    for (int i = 0; i < 8; i++)
#pragma unroll
        for (int j = 0; j < 4; j++) acc[i][j] = 0ull;

    for (int k0 = 0; k0 < DIMc; k0 += 16) {
#pragma unroll
        for (int ii = 0; ii < 2; ii++) {
            int e = t + 256 * ii;
            int row = e >> 2, c4 = e & 3;
            float4 a = *(const float4*)(x + (m0 + row) * DIMc + k0 + 4 * c4);
            As[4 * c4 + 0][row] = a.x; As[4 * c4 + 1][row] = a.y;
            As[4 * c4 + 2][row] = a.z; As[4 * c4 + 3][row] = a.w;
            float4 bvec = *(const float4*)(w + (o0 + row) * DIMc + k0 + 4 * c4);
            Bs[4 * c4 + 0][row] = bvec.x; Bs[4 * c4 + 1][row] = bvec.y;
            Bs[4 * c4 + 2][row] = bvec.z; Bs[4 * c4 + 3][row] = bvec.w;
        }
        __syncthreads();
#pragma unroll
        for (int kk = 0; kk < 16; kk++) {
            unsigned long long a2[8], b2[4];
#pragma unroll
            for (int i = 0; i < 8; i++) { float av = As[kk][8 * ty + i]; a2[i] = pack2(av, av); }
#pragma unroll
            for (int j = 0; j < 4; j++) {
                float2 bv = *(const float2*)&Bs[kk][2 * tx + 32 * j];
                b2[j] = pack2(bv.x, bv.y);
            }
#pragma unroll
            for (int i = 0; i < 8; i++)
#pragma unroll
                for (int j = 0; j < 4; j++) fma2(acc[i][j], a2[i], b2[j]);
        }
        __syncthreads();
    }
#pragma unroll
    for (int i = 0; i < 8; i++) {
        int m = m0 + 8 * ty + i;
        int b = m / Nn, n = m - b * Nn;
#pragma unroll
        for (int j = 0; j < 4; j++) {
            int o = o0 + 2 * tx + 32 * j;
            float2 v2 = unpack2(acc[i][j]);
            qkv_scatter(b, n, o,     v2.x * g_qs[o]     + g_qbb[o]);
            qkv_scatter(b, n, o + 1, v2.y * g_qs[o + 1] + g_qbb[o + 1]);
        }
    }
}

// ---------------- attention: 128 threads, 64 q-rows, 8x8 f32x2 tiles ----------------
// Duplicate-value smem layouts for Q and P so broadcast operands arrive
// pre-packed as f32x2 (no mov.b64 in the hot loops).
__global__ __launch_bounds__(128, 2) void attn_kernel() {
    extern __shared__ float sm[];
    float* q2  = sm;               // [32][132]: q2[kk*132+2r+h] = q[n0+r][kk] (dup)
    float* k_s = q2 + 32 * 132;    // [32][68]:  k_s[kk*68+r]   = k[m0+r][kk]
    float* v_s = k_s + 32 * 68;    // [64][128]: v_s[r*128+d]   = v[m0+r][d]
    float* p2  = v_s + 64 * 128;   // [64][132]: p2[j*132+2r+h] = P[r][j] (dup)

    int n0 = blockIdx.x * 64;
    int h = blockIdx.y, b = blockIdx.z;
    int t = threadIdx.x, tx = t & 15, ty = t >> 4;   // tx 0..15, ty 0..7

    const float* qb = g_q + ((b * Hh + h) * Nn) * KDc;
    const float* kb = g_k + ((b * Hh + h) * Nn) * KDc;
    const float* vb = g_v + ((b * Hh + h) * Nn) * VDc;
    const float* biasb = g_bias + h * Nn * Nn;

    // fill q2 (duplicated)
    for (int e = t; e < 2048; e += 128) {
        int kk = e & 31, r = e >> 5;
        float qv = (n0 + r < Nn) ? qb[(n0 + r) * KDc + kk] : 0.f;
        *(float2*)&q2[kk * 132 + 2 * r] = make_float2(qv, qv);
    }

    unsigned long long o_acc[8][4];
#pragma unroll
    for (int i = 0; i < 8; i++)
#pragma unroll
        for (int c = 0; c < 4; c++) o_acc[i][c] = 0ull;
    float rsum[8];
#pragma unroll
    for (int i = 0; i < 8; i++) rsum[i] = 0.f;

    for (int m0 = 0; m0 < Nn; m0 += 64) {
        __syncthreads();   // prev-iteration PV readers done
        for (int e = t; e < 2048; e += 128) {
            int kk = e & 31, r = e >> 5;
            int m = m0 + r;
            k_s[kk * 68 + r] = (m < Nn) ? kb[m * KDc + kk] : 0.f;
        }
        for (int e = t; e < 2048; e += 128) {
            int r = e >> 5, c4 = e & 31;
            int m = m0 + r;
            *(float4*)&v_s[r * 128 + 4 * c4] =
                (m < Nn) ? *(const float4*)&vb[m * VDc + 4 * c4]
                         : make_float4(0.f, 0.f, 0.f, 0.f);
        }
        __syncthreads();

        // ---- S = Q K^T : 8 rows x 4 cols per thread (cols 2tx,2tx+1,2tx+32,2tx+33)
        unsigned long long sa[8][2];
#pragma unroll
        for (int i = 0; i < 8; i++) { sa[i][0] = 0ull; sa[i][1] = 0ull; }
#pragma unroll 4
        for (int kk = 0; kk < 32; kk++) {
            unsigned long long a2[8];
#pragma unroll
            for (int i2 = 0; i2 < 4; i2++) {
                ulonglong2 qa = *(const ulonglong2*)&q2[kk * 132 + 16 * ty + 4 * i2];
                a2[2 * i2] = qa.x; a2[2 * i2 + 1] = qa.y;
            }
            unsigned long long b0 = *(const unsigned long long*)&k_s[kk * 68 + 2 * tx];
            unsigned long long b1 = *(const unsigned long long*)&k_s[kk * 68 + 2 * tx + 32];
#pragma unroll
            for (int i = 0; i < 8; i++) {
                fma2(sa[i][0], a2[i], b0);
                fma2(sa[i][1], a2[i], b1);
            }
        }

        // ---- bias + exp -> p2 (duplicated, [col][row]); accumulate row sums
        int c0 = m0 + 2 * tx, c1 = m0 + 2 * tx + 32;
#pragma unroll
        for (int i = 0; i < 8; i++) {
            int n = n0 + 8 * ty + i;
            int nc = (n < Nn) ? n : (Nn - 1);
            const float* brow = biasb + nc * Nn;
            float2 bia, bib;
            if (c0 + 1 < Nn) bia = *(const float2*)(brow + c0);
            else { bia.x = (c0 < Nn) ? brow[c0] : 0.f; bia.y = 0.f; }
            if (c1 + 1 < Nn) bib = *(const float2*)(brow + c1);
            else { bib.x = (c1 < Nn) ? brow[c1] : 0.f; bib.y = 0.f; }
            float2 s0 = unpack2(sa[i][0]), s1 = unpack2(sa[i][1]);
            float p00 = (c0     < Nn) ? __expf(s0.x * SCALE + bia.x) : 0.f;
            float p01 = (c0 + 1 < Nn) ? __expf(s0.y * SCALE + bia.y) : 0.f;
            float p10 = (c1     < Nn) ? __expf(s1.x * SCALE + bib.x) : 0.f;
            float p11 = (c1 + 1 < Nn) ? __expf(s1.y * SCALE + bib.y) : 0.f;
            int ro = 16 * ty + 2 * i;
            *(float2*)&p2[(2 * tx)      * 132 + ro] = make_float2(p00, p00);
            *(float2*)&p2[(2 * tx + 1)  * 132 + ro] = make_float2(p01, p01);
            *(float2*)&p2[(2 * tx + 32) * 132 + ro] = make_float2(p10, p10);
            *(float2*)&p2[(2 * tx + 33) * 132 + ro] = make_float2(p11, p11);
            rsum[i] += (p00 + p01) + (p10 + p11);
        }
        __syncthreads();

        // ---- O += P V : 8 rows x 8 cols per thread
#pragma unroll 4
        for (int j = 0; j < 64; j++) {
            unsigned long long pf[8];
#pragma unroll
            for (int i2 = 0; i2 < 4; i2++) {
                ulonglong2 pa = *(const ulonglong2*)&p2[j * 132 + 16 * ty + 4 * i2];
                pf[2 * i2] = pa.x; pf[2 * i2 + 1] = pa.y;
            }
            unsigned long long vf[4];
#pragma unroll
            for (int c = 0; c < 4; c++)
                vf[c] = *(const unsigned long long*)&v_s[j * 128 + 2 * tx + 32 * c];
#pragma unroll
            for (int i = 0; i < 8; i++)
#pragma unroll
                for (int c = 0; c < 4; c++) fma2(o_acc[i][c], pf[i], vf[c]);
        }
    }

    // reduce row sums across the 16 tx lanes
#pragma unroll
    for (int i = 0; i < 8; i++)
#pragma unroll
        for (int off = 8; off > 0; off >>= 1)
            rsum[i] += __shfl_xor_sync(0xffffffffu, rsum[i], off, 16);

    // normalize + hardswish + store
#pragma unroll
    for (int i = 0; i < 8; i++) {
        int n = n0 + 8 * ty + i;
        if (n >= Nn) continue;
        float inv = 1.f / rsum[i];
#pragma unroll
        for (int c = 0; c < 4; c++) {
            float2 ov = unpack2(o_acc[i][c]);
            float o0v = ov.x * inv, o1v = ov.y * inv;
            o0v = o0v * fminf(fmaxf(o0v + 3.f, 0.f), 6.f) * (1.f / 6.f);
            o1v = o1v * fminf(fmaxf(o1v + 3.f, 0.f), 6.f) * (1.f / 6.f);
            *(float2*)&g_o[(b * Nn + n) * VAL_ATTNc + h * VDc + 2 * tx + 32 * c] =
                make_float2(o0v, o1v);
        }
    }
}

// ---------------- proj GEMM: out[m,o] = BN(sum_k g_o[m,k]*w[o,k]) ----------------
__global__ __launch_bounds__(256, 2) void proj_gemm_kernel(const float* __restrict__ w,
                                                           float* __restrict__ out) {
    __shared__ float As[16][136];
    __shared__ float Bs[16][136];
    int m0 = blockIdx.x * 128, o0 = blockIdx.y * 128;
    int t = threadIdx.x, tx = t & 15, ty = t >> 4;

    unsigned long long acc[8][4];
#pragma unroll
    for (int i = 0; i < 8; i++)
#pragma unroll
        for (int j = 0; j < 4; j++) acc[i][j] = 0ull;

    for (int k0 = 0; k0 < VAL_ATTNc; k0 += 16) {
#pragma unroll
        for (int ii = 0; ii < 2; ii++) {
            int e = t + 256 * ii;
            int row = e >> 2, c4 = e & 3;
            float4 a = *(const float4*)(g_o + (m0 + row) * VAL_ATTNc + k0 + 4 * c4);
            As[4 * c4 + 0][row] = a.x; As[4 * c4 + 1][row] = a.y;
            As[4 * c4 + 2][row] = a.z; As[4 * c4 + 3][row] = a.w;
            float4 bvec = *(const float4*)(w + (o0 + row) * VAL_ATTNc + k0 + 4 * c4);
            Bs[4 * c4 + 0][row] = bvec.x; Bs[4 * c4 + 1][row] = bvec.y;
            Bs[4 * c4 + 2][row] = bvec.z; Bs[4 * c4 + 3][row] = bvec.w;
        }
        __syncthreads();
#pragma unroll
        for (int kk = 0; kk < 16; kk++) {
            unsigned long long a2[8], b2[4];
#pragma unroll
            for (int i = 0; i < 8; i++) { float av = As[kk][8 * ty + i]; a2[i] = pack2(av, av); }
#pragma unroll
            for (int j = 0; j < 4; j++) {
                float2 bv = *(const float2*)&Bs[kk][2 * tx + 32 * j];
                b2[j] = pack2(bv.x, bv.y);
            }
#pragma unroll
            for (int i = 0; i < 8; i++)
#pragma unroll
                for (int j = 0; j < 4; j++) fma2(acc[i][j], a2[i], b2[j]);
        }
        __syncthreads();
    }
#pragma unroll
    for (int i = 0; i < 8; i++) {
        int m = m0 + 8 * ty + i;
#pragma unroll
        for (int j = 0; j < 4; j++) {
            int o = o0 + 2 * tx + 32 * j;
            float2 v2 = unpack2(acc[i][j]);
            float y0 = v2.x * g_ps[o]     + g_pbb[o];
            float y1 = v2.y * g_ps[o + 1] + g_pbb[o + 1];
            *(float2*)&out[m * DIMc + o] = make_float2(y0, y1);
        }
    }
}

// ---------------- launch ----------------
extern "C" void kernel_launch(void* const* d_in, const int* in_sizes, int n_in,
                              void* d_out, int out_size) {
    (void)in_sizes; (void)n_in; (void)out_size;
    const float* x      = (const float*)d_in[0];
    const float* qkv_w  = (const float*)d_in[1];
    const float* qkv_g  = (const float*)d_in[2];
    const float* qkv_b  = (const float*)d_in[3];
    const float* qkv_m  = (const float*)d_in[4];
    const float* qkv_v  = (const float*)d_in[5];
    const float* ab     = (const float*)d_in[6];
    const float* proj_w = (const float*)d_in[7];
    const float* proj_g = (const float*)d_in[8];
    const float* proj_b = (const float*)d_in[9];
    const float* proj_m = (const float*)d_in[10];
    const float* proj_v = (const float*)d_in[11];
    const int*   idxs   = (const int*)d_in[12];
    float* out = (float*)d_out;

    bn_coef_kernel<<<6, 256>>>(qkv_g, qkv_b, qkv_m, qkv_v, proj_g, proj_b, proj_m, proj_v);
    bias_kernel<<<(Nn * Nn + 255) / 256, 256>>>(ab, idxs);
    qkv_gemm_kernel<<<dim3(196, 12), 256>>>(x, qkv_w);

    const int ATTN_SMEM = (32 * 132 + 32 * 68 + 64 * 128 + 64 * 132) * 4;  // 92160 B
    cudaFuncSetAttribute(attn_kernel, cudaFuncAttributeMaxDynamicSharedMemorySize, ATTN_SMEM);
    attn_kernel<<<dim3(13, 8, 32), 128, ATTN_SMEM>>>();

    proj_gemm_kernel<<<dim3(196, 4), 256>>>(proj_w, out);
}

// round 5
// speedup vs baseline: 1.0656x; 1.0656x over previous
#include <cuda_runtime.h>
#include <math.h>

#define Bc 32
#define Nn 784
#define DIMc 512
#define Hh 8
#define KDc 32
#define VDc 128
#define QKV_OUTc 1536
#define VAL_ATTNc 1024
#define SCALE 0.17677669529663687f

// ---------------- scratch (static device globals) ----------------
__device__ float g_q[Bc * Hh * Nn * KDc];          // [b][h][n][32]
__device__ float g_k[Bc * Hh * Nn * KDc];          // [b][h][n][32]
__device__ float g_v[Bc * Hh * Nn * VDc];          // [b][h][n][128]
__device__ float g_o[Bc * Nn * VAL_ATTNc];         // [b][n][h*128+d]
__device__ float g_bias[Hh * Nn * Nn];             // [h][n][m]
__device__ float g_qs[QKV_OUTc], g_qbb[QKV_OUTc];
__device__ float g_ps[DIMc], g_pbb[DIMc];

// ---------------- f32x2 helpers (FFMA2: 2x fp32 FMA rate on sm_103a) ----------------
static __device__ __forceinline__ unsigned long long pack2(float lo, float hi) {
    unsigned long long r;
    asm("mov.b64 %0, {%1, %2};" : "=l"(r) : "r"(__float_as_uint(lo)), "r"(__float_as_uint(hi)));
    return r;
}
static __device__ __forceinline__ float2 unpack2(unsigned long long v) {
    unsigned int lo, hi;
    asm("mov.b64 {%0, %1}, %2;" : "=r"(lo), "=r"(hi) : "l"(v));
    return make_float2(__uint_as_float(lo), __uint_as_float(hi));
}
static __device__ __forceinline__ void fma2(unsigned long long& d, unsigned long long a, unsigned long long b) {
    asm("fma.rn.f32x2 %0, %1, %2, %0;" : "+l"(d) : "l"(a), "l"(b));
}

// ---------------- BN coefficient folding ----------------
__global__ void bn_coef_kernel(const float* __restrict__ qg, const float* __restrict__ qb,
                               const float* __restrict__ qm, const float* __restrict__ qv,
                               const float* __restrict__ pg, const float* __restrict__ pb,
                               const float* __restrict__ pm, const float* __restrict__ pv) {
    int i = blockIdx.x * 256 + threadIdx.x;
    if (i < QKV_OUTc) {
        float s = qg[i] * rsqrtf(qv[i] + 1e-5f);
        g_qs[i] = s;
        g_qbb[i] = qb[i] - qm[i] * s;
    }
    if (i < DIMc) {
        float s = pg[i] * rsqrtf(pv[i] + 1e-5f);
        g_ps[i] = s;
        g_pbb[i] = pb[i] - pm[i] * s;
    }
}

// ---------------- bias gather: g_bias[h][n][m] = ab[h, idxs[n,m]] ----------------
__global__ void bias_kernel(const float* __restrict__ ab, const int* __restrict__ idxs) {
    int nm = blockIdx.x * 256 + threadIdx.x;
    if (nm < Nn * Nn) {
        int idx = idxs[nm];
#pragma unroll
        for (int h = 0; h < Hh; h++)
            g_bias[h * Nn * Nn + nm] = ab[h * Nn + idx];
    }
}

// ---------------- QKV GEMM: C[m,o] = sum_k x[m,k]*w[o,k], + BN, scatter ----------------
static __device__ __forceinline__ void qkv_scatter(int b, int n, int o, float y) {
    int h = o / 192, r = o - h * 192;
    if (r < KDc)            g_q[((b * Hh + h) * Nn + n) * KDc + r] = y;
    else if (r < 2 * KDc)   g_k[((b * Hh + h) * Nn + n) * KDc + (r - KDc)] = y;
    else                    g_v[((b * Hh + h) * Nn + n) * VDc + (r - 2 * KDc)] = y;
}

__global__ __launch_bounds__(256, 2) void qkv_gemm_kernel(const float* __restrict__ x,
                                                          const float* __restrict__ w) {
    __shared__ float As[16][136];   // [k][row], padded
    __shared__ float Bs[16][136];
    int m0 = blockIdx.x * 128, o0 = blockIdx.y * 128;
    int t = threadIdx.x, tx = t & 15, ty = t >> 4;

    unsigned long long acc[8][4];
#pragma unroll
    for (int i = 0; i < 8; i++)
#pragma unroll
        for (int j = 0; j < 4; j++) acc[i][j] = 0ull;

    for (int k0 = 0; k0 < DIMc; k0 += 16) {
#pragma unroll
        for (int ii = 0; ii < 2; ii++) {
            int e = t + 256 * ii;
            int row = e >> 2, c4 = e & 3;
            float4 a = *(const float4*)(x + (m0 + row) * DIMc + k0 + 4 * c4);
            As[4 * c4 + 0][row] = a.x; As[4 * c4 + 1][row] = a.y;
            As[4 * c4 + 2][row] = a.z; As[4 * c4 + 3][row] = a.w;
            float4 bvec = *(const float4*)(w + (o0 + row) * DIMc + k0 + 4 * c4);
            Bs[4 * c4 + 0][row] = bvec.x; Bs[4 * c4 + 1][row] = bvec.y;
            Bs[4 * c4 + 2][row] = bvec.z; Bs[4 * c4 + 3][row] = bvec.w;
        }
        __syncthreads();
#pragma unroll
        for (int kk = 0; kk < 16; kk++) {
            unsigned long long a2[8], b2[4];
#pragma unroll
            for (int i = 0; i < 8; i++) { float av = As[kk][8 * ty + i]; a2[i] = pack2(av, av); }
#pragma unroll
            for (int j = 0; j < 4; j++) {
                float2 bv = *(const float2*)&Bs[kk][2 * tx + 32 * j];
                b2[j] = pack2(bv.x, bv.y);
            }
#pragma unroll
            for (int i = 0; i < 8; i++)
#pragma unroll
                for (int j = 0; j < 4; j++) fma2(acc[i][j], a2[i], b2[j]);
        }
        __syncthreads();
    }
#pragma unroll
    for (int i = 0; i < 8; i++) {
        int m = m0 + 8 * ty + i;
        int b = m / Nn, n = m - b * Nn;
#pragma unroll
        for (int j = 0; j < 4; j++) {
            int o = o0 + 2 * tx + 32 * j;
            float2 v2 = unpack2(acc[i][j]);
            qkv_scatter(b, n, o,     v2.x * g_qs[o]     + g_qbb[o]);
            qkv_scatter(b, n, o + 1, v2.y * g_qs[o + 1] + g_qbb[o + 1]);
        }
    }
}

// ---------------- attention: 256 threads, 64 q-rows, 4x8 f32x2 tiles ----------------
// Dup-value smem for Q and P (broadcast operands pre-packed as f32x2, no movs),
// 256 threads for 16 warps/SM at 2 CTAs (R4's 8 warps starved issue).
__global__ __launch_bounds__(256, 2) void attn_kernel() {
    extern __shared__ float sm[];
    float* q2  = sm;               // [32][132]: q2[kk*132+2r+h] = q[n0+r][kk] (dup)
    float* k_s = q2 + 32 * 132;    // [32][68]:  k_s[kk*68+r]   = k[m0+r][kk]
    float* v_s = k_s + 32 * 68;    // [64][128]: v_s[r*128+d]   = v[m0+r][d]
    float* p2  = v_s + 64 * 128;   // [64][132]: p2[j*132+2r+h] = P[r][j] (dup)

    int n0 = blockIdx.x * 64;
    int h = blockIdx.y, b = blockIdx.z;
    int t = threadIdx.x, tx = t & 15, ty = t >> 4;   // tx 0..15 (cols), ty 0..15 (4 rows each)

    const float* qb = g_q + ((b * Hh + h) * Nn) * KDc;
    const float* kb = g_k + ((b * Hh + h) * Nn) * KDc;
    const float* vb = g_v + ((b * Hh + h) * Nn) * VDc;
    const float* biasb = g_bias + h * Nn * Nn;

    // fill q2 (duplicated)
    for (int e = t; e < 2048; e += 256) {
        int kk = e & 31, r = e >> 5;
        float qv = (n0 + r < Nn) ? qb[(n0 + r) * KDc + kk] : 0.f;
        *(float2*)&q2[kk * 132 + 2 * r] = make_float2(qv, qv);
    }

    unsigned long long o_acc[4][4];
#pragma unroll
    for (int i = 0; i < 4; i++)
#pragma unroll
        for (int c = 0; c < 4; c++) o_acc[i][c] = 0ull;
    float rsum[4] = {0.f, 0.f, 0.f, 0.f};

    for (int m0 = 0; m0 < Nn; m0 += 64) {
        __syncthreads();   // prev-iteration PV readers done before overwrite
        for (int e = t; e < 2048; e += 256) {
            int kk = e & 31, r = e >> 5;
            int m = m0 + r;
            k_s[kk * 68 + r] = (m < Nn) ? kb[m * KDc + kk] : 0.f;
        }
        for (int e = t; e < 2048; e += 256) {
            int r = e >> 5, c4 = e & 31;
            int m = m0 + r;
            *(float4*)&v_s[r * 128 + 4 * c4] =
                (m < Nn) ? *(const float4*)&vb[m * VDc + 4 * c4]
                         : make_float4(0.f, 0.f, 0.f, 0.f);
        }
        __syncthreads();

        // ---- S = Q K^T : 4 rows x 4 cols per thread (cols 2tx,2tx+1,2tx+32,2tx+33)
        unsigned long long sa[4][2];
#pragma unroll
        for (int i = 0; i < 4; i++) { sa[i][0] = 0ull; sa[i][1] = 0ull; }
#pragma unroll 8
        for (int kk = 0; kk < 32; kk++) {
            ulonglong2 qa = *(const ulonglong2*)&q2[kk * 132 + 8 * ty];
            ulonglong2 qc = *(const ulonglong2*)&q2[kk * 132 + 8 * ty + 4];
            unsigned long long a2[4] = {qa.x, qa.y, qc.x, qc.y};
            unsigned long long b0 = *(const unsigned long long*)&k_s[kk * 68 + 2 * tx];
            unsigned long long b1 = *(const unsigned long long*)&k_s[kk * 68 + 2 * tx + 32];
#pragma unroll
            for (int i = 0; i < 4; i++) {
                fma2(sa[i][0], a2[i], b0);
                fma2(sa[i][1], a2[i], b1);
            }
        }

        // ---- bias + exp -> p2 (duplicated, [col][row]); accumulate row sums
        int c0 = m0 + 2 * tx, c1 = m0 + 2 * tx + 32;
#pragma unroll
        for (int i = 0; i < 4; i++) {
            int n = n0 + 4 * ty + i;
            int nc = (n < Nn) ? n : (Nn - 1);
            const float* brow = biasb + nc * Nn;
            float2 bia, bib;
            if (c0 + 1 < Nn) bia = *(const float2*)(brow + c0);
            else { bia.x = (c0 < Nn) ? brow[c0] : 0.f; bia.y = 0.f; }
            if (c1 + 1 < Nn) bib = *(const float2*)(brow + c1);
            else { bib.x = (c1 < Nn) ? brow[c1] : 0.f; bib.y = 0.f; }
            float2 s0 = unpack2(sa[i][0]), s1 = unpack2(sa[i][1]);
            float p00 = (c0     < Nn) ? __expf(s0.x * SCALE + bia.x) : 0.f;
            float p01 = (c0 + 1 < Nn) ? __expf(s0.y * SCALE + bia.y) : 0.f;
            float p10 = (c1     < Nn) ? __expf(s1.x * SCALE + bib.x) : 0.f;
            float p11 = (c1 + 1 < Nn) ? __expf(s1.y * SCALE + bib.y) : 0.f;
            int ro = 8 * ty + 2 * i;
            *(float2*)&p2[(2 * tx)      * 132 + ro] = make_float2(p00, p00);
            *(float2*)&p2[(2 * tx + 1)  * 132 + ro] = make_float2(p01, p01);
            *(float2*)&p2[(2 * tx + 32) * 132 + ro] = make_float2(p10, p10);
            *(float2*)&p2[(2 * tx + 33) * 132 + ro] = make_float2(p11, p11);
            rsum[i] += (p00 + p01) + (p10 + p11);
        }
        __syncthreads();

        // ---- O += P V : 4 rows x 8 cols per thread
#pragma unroll 8
        for (int j = 0; j < 64; j++) {
            ulonglong2 pa = *(const ulonglong2*)&p2[j * 132 + 8 * ty];
            ulonglong2 pc = *(const ulonglong2*)&p2[j * 132 + 8 * ty + 4];
            unsigned long long pf[4] = {pa.x, pa.y, pc.x, pc.y};
            unsigned long long vf[4];
#pragma unroll
            for (int c = 0; c < 4; c++)
                vf[c] = *(const unsigned long long*)&v_s[j * 128 + 2 * tx + 32 * c];
#pragma unroll
            for (int i = 0; i < 4; i++)
#pragma unroll
                for (int c = 0; c < 4; c++) fma2(o_acc[i][c], pf[i], vf[c]);
        }
    }

    // reduce row sums across the 16 tx lanes
#pragma unroll
    for (int i = 0; i < 4; i++)
#pragma unroll
        for (int off = 8; off > 0; off >>= 1)
            rsum[i] += __shfl_xor_sync(0xffffffffu, rsum[i], off, 16);

    // normalize + hardswish + store
#pragma unroll
    for (int i = 0; i < 4; i++) {
        int n = n0 + 4 * ty + i;
        if (n >= Nn) continue;
        float inv = 1.f / rsum[i];
#pragma unroll
        for (int c = 0; c < 4; c++) {
            float2 ov = unpack2(o_acc[i][c]);
            float o0v = ov.x * inv, o1v = ov.y * inv;
            o0v = o0v * fminf(fmaxf(o0v + 3.f, 0.f), 6.f) * (1.f / 6.f);
            o1v = o1v * fminf(fmaxf(o1v + 3.f, 0.f), 6.f) * (1.f / 6.f);
            *(float2*)&g_o[(b * Nn + n) * VAL_ATTNc + h * VDc + 2 * tx + 32 * c] =
                make_float2(o0v, o1v);
        }
    }
}

// ---------------- proj GEMM: out[m,o] = BN(sum_k g_o[m,k]*w[o,k]) ----------------
__global__ __launch_bounds__(256, 2) void proj_gemm_kernel(const float* __restrict__ w,
                                                           float* __restrict__ out) {
    __shared__ float As[16][136];
    __shared__ float Bs[16][136];
    int m0 = blockIdx.x * 128, o0 = blockIdx.y * 128;
    int t = threadIdx.x, tx = t & 15, ty = t >> 4;

    unsigned long long acc[8][4];
#pragma unroll
    for (int i = 0; i < 8; i++)
#pragma unroll
        for (int j = 0; j < 4; j++) acc[i][j] = 0ull;

    for (int k0 = 0; k0 < VAL_ATTNc; k0 += 16) {
#pragma unroll
        for (int ii = 0; ii < 2; ii++) {
            int e = t + 256 * ii;
            int row = e >> 2, c4 = e & 3;
            float4 a = *(const float4*)(g_o + (m0 + row) * VAL_ATTNc + k0 + 4 * c4);
            As[4 * c4 + 0][row] = a.x; As[4 * c4 + 1][row] = a.y;
            As[4 * c4 + 2][row] = a.z; As[4 * c4 + 3][row] = a.w;
            float4 bvec = *(const float4*)(w + (o0 + row) * VAL_ATTNc + k0 + 4 * c4);
            Bs[4 * c4 + 0][row] = bvec.x; Bs[4 * c4 + 1][row] = bvec.y;
            Bs[4 * c4 + 2][row] = bvec.z; Bs[4 * c4 + 3][row] = bvec.w;
        }
        __syncthreads();
#pragma unroll
        for (int kk = 0; kk < 16; kk++) {
            unsigned long long a2[8], b2[4];
#pragma unroll
            for (int i = 0; i < 8; i++) { float av = As[kk][8 * ty + i]; a2[i] = pack2(av, av); }
#pragma unroll
            for (int j = 0; j < 4; j++) {
                float2 bv = *(const float2*)&Bs[kk][2 * tx + 32 * j];
                b2[j] = pack2(bv.x, bv.y);
            }
#pragma unroll
            for (int i = 0; i < 8; i++)
#pragma unroll
                for (int j = 0; j < 4; j++) fma2(acc[i][j], a2[i], b2[j]);
        }
        __syncthreads();
    }
#pragma unroll
    for (int i = 0; i < 8; i++) {
        int m = m0 + 8 * ty + i;
#pragma unroll
        for (int j = 0; j < 4; j++) {
            int o = o0 + 2 * tx + 32 * j;
            float2 v2 = unpack2(acc[i][j]);
            float y0 = v2.x * g_ps[o]     + g_pbb[o];
            float y1 = v2.y * g_ps[o + 1] + g_pbb[o + 1];
            *(float2*)&out[m * DIMc + o] = make_float2(y0, y1);
        }
    }
}

// ---------------- launch ----------------
extern "C" void kernel_launch(void* const* d_in, const int* in_sizes, int n_in,
                              void* d_out, int out_size) {
    (void)in_sizes; (void)n_in; (void)out_size;
    const float* x      = (const float*)d_in[0];
    const float* qkv_w  = (const float*)d_in[1];
    const float* qkv_g  = (const float*)d_in[2];
    const float* qkv_b  = (const float*)d_in[3];
    const float* qkv_m  = (const float*)d_in[4];
    const float* qkv_v  = (const float*)d_in[5];
    const float* ab     = (const float*)d_in[6];
    const float* proj_w = (const float*)d_in[7];
    const float* proj_g = (const float*)d_in[8];
    const float* proj_b = (const float*)d_in[9];
    const float* proj_m = (const float*)d_in[10];
    const float* proj_v = (const float*)d_in[11];
    const int*   idxs   = (const int*)d_in[12];
    float* out = (float*)d_out;

    bn_coef_kernel<<<6, 256>>>(qkv_g, qkv_b, qkv_m, qkv_v, proj_g, proj_b, proj_m, proj_v);
    bias_kernel<<<(Nn * Nn + 255) / 256, 256>>>(ab, idxs);
    qkv_gemm_kernel<<<dim3(196, 12), 256>>>(x, qkv_w);

    const int ATTN_SMEM = (32 * 132 + 32 * 68 + 64 * 128 + 64 * 132) * 4;  // 92160 B
    cudaFuncSetAttribute(attn_kernel, cudaFuncAttributeMaxDynamicSharedMemorySize, ATTN_SMEM);
    attn_kernel<<<dim3(13, 8, 32), 256, ATTN_SMEM>>>();

    proj_gemm_kernel<<<dim3(196, 4), 256>>>(proj_w, out);
}

// round 7
// speedup vs baseline: 1.5199x; 1.4263x over previous
#include <cuda_runtime.h>
#include <cuda_bf16.h>
#include <math.h>
#include <cstdint>

#define Bc 32
#define Nn 784
#define DIMc 512
#define Hh 8
#define KDc 32
#define VDc 128
#define QKV_OUTc 1536
#define VAL_ATTNc 1024
#define SCALE 0.17677669529663687f

// ---------------- scratch (static device globals) ----------------
__device__ float g_q[Bc * Hh * Nn * KDc];          // [b][h][n][32]
__device__ float g_k[Bc * Hh * Nn * KDc];          // [b][h][n][32]
__device__ float g_v[Bc * Hh * Nn * VDc];          // [b][h][n][128]
__device__ float g_o[Bc * Nn * VAL_ATTNc];         // [b][n][h*128+d]
__device__ float g_bias[Hh * Nn * Nn];             // [h][n][m]
__device__ float g_qs[QKV_OUTc], g_qbb[QKV_OUTc];
__device__ float g_ps[DIMc], g_pbb[DIMc];

// split-bf16 buffers
__device__ __nv_bfloat16 g_xh[Bc * Nn * DIMc],  g_xl[Bc * Nn * DIMc];
__device__ __nv_bfloat16 g_wqh[QKV_OUTc * DIMc], g_wql[QKV_OUTc * DIMc];
__device__ __nv_bfloat16 g_oh[Bc * Nn * VAL_ATTNc], g_ol[Bc * Nn * VAL_ATTNc];
__device__ __nv_bfloat16 g_wph[DIMc * VAL_ATTNc], g_wpl[DIMc * VAL_ATTNc];

// ---------------- f32x2 helpers ----------------
static __device__ __forceinline__ unsigned long long pack2(float lo, float hi) {
    unsigned long long r;
    asm("mov.b64 %0, {%1, %2};" : "=l"(r) : "r"(__float_as_uint(lo)), "r"(__float_as_uint(hi)));
    return r;
}
static __device__ __forceinline__ float2 unpack2(unsigned long long v) {
    unsigned int lo, hi;
    asm("mov.b64 {%0, %1}, %2;" : "=r"(lo), "=r"(hi) : "l"(v));
    return make_float2(__uint_as_float(lo), __uint_as_float(hi));
}
static __device__ __forceinline__ void fma2(unsigned long long& d, unsigned long long a, unsigned long long b) {
    asm("fma.rn.f32x2 %0, %1, %2, %0;" : "+l"(d) : "l"(a), "l"(b));
}

// ---------------- bf16 mma.sync (base PTX, compiles under compute_103) ----------------
static __device__ __forceinline__ void mma_bf16(float* d, const unsigned* a, const unsigned* b) {
    asm("mma.sync.aligned.m16n8k16.row.col.f32.bf16.bf16.f32 "
        "{%0,%1,%2,%3}, {%4,%5,%6,%7}, {%8,%9}, {%0,%1,%2,%3};"
        : "+f"(d[0]), "+f"(d[1]), "+f"(d[2]), "+f"(d[3])
        : "r"(a[0]), "r"(a[1]), "r"(a[2]), "r"(a[3]), "r"(b[0]), "r"(b[1]));
}

// ---------------- BN coefficient folding ----------------
__global__ void bn_coef_kernel(const float* __restrict__ qg, const float* __restrict__ qb,
                               const float* __restrict__ qm, const float* __restrict__ qv,
                               const float* __restrict__ pg, const float* __restrict__ pb,
                               const float* __restrict__ pm, const float* __restrict__ pv) {
    int i = blockIdx.x * 256 + threadIdx.x;
    if (i < QKV_OUTc) {
        float s = qg[i] * rsqrtf(qv[i] + 1e-5f);
        g_qs[i] = s;
        g_qbb[i] = qb[i] - qm[i] * s;
    }
    if (i < DIMc) {
        float s = pg[i] * rsqrtf(pv[i] + 1e-5f);
        g_ps[i] = s;
        g_pbb[i] = pb[i] - pm[i] * s;
    }
}

// ---------------- bias gather ----------------
__global__ void bias_kernel(const float* __restrict__ ab, const int* __restrict__ idxs) {
    int nm = blockIdx.x * 256 + threadIdx.x;
    if (nm < Nn * Nn) {
        int idx = idxs[nm];
#pragma unroll
        for (int h = 0; h < Hh; h++)
            g_bias[h * Nn * Nn + nm] = ab[h * Nn + idx];
    }
}

// ---------------- fp32 -> hi/lo bf16 conversion ----------------
static __device__ __forceinline__ unsigned pk_bf(__nv_bfloat16 a, __nv_bfloat16 b) {
    return ((unsigned)__bfloat16_as_ushort(b) << 16) | (unsigned)__bfloat16_as_ushort(a);
}
__global__ void cvt_hilo_kernel(const float* __restrict__ s, int which, int n4) {
    int i = blockIdx.x * 256 + threadIdx.x;
    if (i >= n4) return;
    const float4* sp;
    __nv_bfloat16 *h, *l;
    if (which == 0)      { sp = (const float4*)s;   h = g_xh;  l = g_xl;  }
    else if (which == 1) { sp = (const float4*)s;   h = g_wqh; l = g_wql; }
    else if (which == 2) { sp = (const float4*)g_o; h = g_oh;  l = g_ol;  }
    else                 { sp = (const float4*)s;   h = g_wph; l = g_wpl; }
    float4 v = sp[i];
    __nv_bfloat16 h0 = __float2bfloat16(v.x), h1 = __float2bfloat16(v.y);
    __nv_bfloat16 h2 = __float2bfloat16(v.z), h3 = __float2bfloat16(v.w);
    __nv_bfloat16 l0 = __float2bfloat16(v.x - __bfloat162float(h0));
    __nv_bfloat16 l1 = __float2bfloat16(v.y - __bfloat162float(h1));
    __nv_bfloat16 l2 = __float2bfloat16(v.z - __bfloat162float(h2));
    __nv_bfloat16 l3 = __float2bfloat16(v.w - __bfloat162float(h3));
    ((uint2*)h)[i] = make_uint2(pk_bf(h0, h1), pk_bf(h2, h3));
    ((uint2*)l)[i] = make_uint2(pk_bf(l0, l1), pk_bf(l2, l3));
}

// ---------------- qkv scatter helper ----------------
static __device__ __forceinline__ void qkv_scatter(int b, int n, int o, float y) {
    int h = o / 192, r = o - h * 192;
    if (r < KDc)            g_q[((b * Hh + h) * Nn + n) * KDc + r] = y;
    else if (r < 2 * KDc)   g_k[((b * Hh + h) * Nn + n) * KDc + (r - KDc)] = y;
    else                    g_v[((b * Hh + h) * Nn + n) * VDc + (r - 2 * KDc)] = y;
}

// ---------------- split-bf16 mma.sync GEMM: C[128m x 128n] = A[m,k]*B[n,k]^T ----------------
// smem row stride 40 bf16 (80B = 20 banks): lane (g,tg) -> bank (20g+tg)%32, all distinct.
#define SSTR 40
__global__ __launch_bounds__(256, 2) void mma_gemm_kernel(int mode, float* __restrict__ out) {
    __shared__ __align__(16) __nv_bfloat16 Ah_s[128 * SSTR];
    __shared__ __align__(16) __nv_bfloat16 Al_s[128 * SSTR];
    __shared__ __align__(16) __nv_bfloat16 Bh_s[128 * SSTR];
    __shared__ __align__(16) __nv_bfloat16 Bl_s[128 * SSTR];

    int t = threadIdx.x;
    int lane = t & 31, wid = t >> 5;
    int g = lane >> 2, tg = lane & 3;
    int warp_m = wid >> 2, warp_n = wid & 3;    // 2 x 4 warp grid
    int m0 = blockIdx.x * 128, o0 = blockIdx.y * 128;

    const __nv_bfloat16 *Ah, *Al, *Bh, *Bl;
    int K;
    if (mode == 0) { Ah = g_xh; Al = g_xl; Bh = g_wqh; Bl = g_wql; K = DIMc; }
    else           { Ah = g_oh; Al = g_ol; Bh = g_wph; Bl = g_wpl; K = VAL_ATTNc; }

    float acc[4][4][4];
#pragma unroll
    for (int i = 0; i < 4; i++)
#pragma unroll
        for (int j = 0; j < 4; j++)
#pragma unroll
            for (int c = 0; c < 4; c++) acc[i][j][c] = 0.f;

    for (int k0 = 0; k0 < K; k0 += 32) {
        // fill: 128 rows x 32 bf16 per operand; 4 x uint4 per row
#pragma unroll
        for (int ii = 0; ii < 2; ii++) {
            int e = t + 256 * ii;                 // 0..511
            int r = e >> 2, c = e & 3;
            size_t ga = (size_t)(m0 + r) * K + k0 + 8 * c;
            size_t gb = (size_t)(o0 + r) * K + k0 + 8 * c;
            int so = r * SSTR + 8 * c;
            *(uint4*)&Ah_s[so] = *(const uint4*)&Ah[ga];
            *(uint4*)&Al_s[so] = *(const uint4*)&Al[ga];
            *(uint4*)&Bh_s[so] = *(const uint4*)&Bh[gb];
            *(uint4*)&Bl_s[so] = *(const uint4*)&Bl[gb];
        }
        __syncthreads();
#pragma unroll
        for (int kk = 0; kk < 2; kk++) {
            int kb = kk * 16 + 2 * tg;
            unsigned ah[4][4], al[4][4], bh[4][2], bl[4][2];
#pragma unroll
            for (int mi = 0; mi < 4; mi++) {
                int r0 = warp_m * 64 + mi * 16 + g;
                ah[mi][0] = *(const unsigned*)&Ah_s[r0 * SSTR + kb];
                ah[mi][1] = *(const unsigned*)&Ah_s[(r0 + 8) * SSTR + kb];
                ah[mi][2] = *(const unsigned*)&Ah_s[r0 * SSTR + kb + 8];
                ah[mi][3] = *(const unsigned*)&Ah_s[(r0 + 8) * SSTR + kb + 8];
                al[mi][0] = *(const unsigned*)&Al_s[r0 * SSTR + kb];
                al[mi][1] = *(const unsigned*)&Al_s[(r0 + 8) * SSTR + kb];
                al[mi][2] = *(const unsigned*)&Al_s[r0 * SSTR + kb + 8];
                al[mi][3] = *(const unsigned*)&Al_s[(r0 + 8) * SSTR + kb + 8];
            }
#pragma unroll
            for (int nj = 0; nj < 4; nj++) {
                int n = warp_n * 32 + nj * 8 + g;
                bh[nj][0] = *(const unsigned*)&Bh_s[n * SSTR + kb];
                bh[nj][1] = *(const unsigned*)&Bh_s[n * SSTR + kb + 8];
                bl[nj][0] = *(const unsigned*)&Bl_s[n * SSTR + kb];
                bl[nj][1] = *(const unsigned*)&Bl_s[n * SSTR + kb + 8];
            }
#pragma unroll
            for (int mi = 0; mi < 4; mi++)
#pragma unroll
                for (int nj = 0; nj < 4; nj++) {
                    mma_bf16(acc[mi][nj], ah[mi], bh[nj]);
                    mma_bf16(acc[mi][nj], ah[mi], bl[nj]);
                    mma_bf16(acc[mi][nj], al[mi], bh[nj]);
                }
        }
        __syncthreads();
    }

    // epilogue
#pragma unroll
    for (int mi = 0; mi < 4; mi++) {
        int m_lo = m0 + warp_m * 64 + mi * 16 + g;
        int m_hi = m_lo + 8;
        if (mode == 0) {
            int b0 = m_lo / Nn, n0q = m_lo - b0 * Nn;
            int b1 = m_hi / Nn, n1q = m_hi - b1 * Nn;
#pragma unroll
            for (int nj = 0; nj < 4; nj++) {
                int o = o0 + warp_n * 32 + nj * 8 + 2 * tg;
                qkv_scatter(b0, n0q, o,     acc[mi][nj][0] * g_qs[o]     + g_qbb[o]);
                qkv_scatter(b0, n0q, o + 1, acc[mi][nj][1] * g_qs[o + 1] + g_qbb[o + 1]);
                qkv_scatter(b1, n1q, o,     acc[mi][nj][2] * g_qs[o]     + g_qbb[o]);
                qkv_scatter(b1, n1q, o + 1, acc[mi][nj][3] * g_qs[o + 1] + g_qbb[o + 1]);
            }
        } else {
#pragma unroll
            for (int nj = 0; nj < 4; nj++) {
                int o = o0 + warp_n * 32 + nj * 8 + 2 * tg;
                float s0 = g_ps[o], s1 = g_ps[o + 1];
                float c0 = g_pbb[o], c1 = g_pbb[o + 1];
                *(float2*)&out[(size_t)m_lo * DIMc + o] =
                    make_float2(acc[mi][nj][0] * s0 + c0, acc[mi][nj][1] * s1 + c1);
                *(float2*)&out[(size_t)m_hi * DIMc + o] =
                    make_float2(acc[mi][nj][2] * s0 + c0, acc[mi][nj][3] * s1 + c1);
            }
        }
    }
}

// ---------------- attention (exact R1 version: measured 1407us) ----------------
__global__ __launch_bounds__(256) void attn_kernel() {
    extern __shared__ float sm[];
    float* q_s = sm;              // [32][68]  (k-major, padded)
    float* k_s = q_s + 32 * 68;   // [32][68]
    float* v_s = k_s + 32 * 68;   // [64][128]
    float* p_s = v_s + 64 * 128;  // [64 col][69 row]

    int n0 = blockIdx.x * 64;
    int h = blockIdx.y, b = blockIdx.z;
    int t = threadIdx.x, tx = t & 15, ty = t >> 4;

    const float* qb = g_q + ((b * Hh + h) * Nn) * KDc;
    const float* kb = g_k + ((b * Hh + h) * Nn) * KDc;
    const float* vb = g_v + ((b * Hh + h) * Nn) * VDc;
    const float* biasb = g_bias + h * Nn * Nn;

    for (int e = t; e < 2048; e += 256) {
        int r = e >> 5, kk = e & 31;
        int n = n0 + r;
        q_s[kk * 68 + r] = (n < Nn) ? qb[n * KDc + kk] : 0.f;
    }

    unsigned long long o_acc[4][4];
#pragma unroll
    for (int i = 0; i < 4; i++)
#pragma unroll
        for (int c = 0; c < 4; c++) o_acc[i][c] = 0ull;
    float rsum[4] = {0.f, 0.f, 0.f, 0.f};

    for (int m0 = 0; m0 < Nn; m0 += 64) {
        __syncthreads();
        for (int e = t; e < 2048; e += 256) {
            int r = e >> 5, kk = e & 31;
            int m = m0 + r;
            k_s[kk * 68 + r] = (m < Nn) ? kb[m * KDc + kk] : 0.f;
        }
        for (int e = t; e < 8192; e += 256) {
            int r = e >> 7, c = e & 127;
            int m = m0 + r;
            v_s[r * 128 + c] = (m < Nn) ? vb[m * VDc + c] : 0.f;
        }
        __syncthreads();

        unsigned long long sa[4][2];
#pragma unroll
        for (int i = 0; i < 4; i++) { sa[i][0] = 0ull; sa[i][1] = 0ull; }
#pragma unroll 8
        for (int kk = 0; kk < 32; kk++) {
            unsigned long long a2[4], b2[2];
#pragma unroll
            for (int i = 0; i < 4; i++) { float av = q_s[kk * 68 + 4 * ty + i]; a2[i] = pack2(av, av); }
#pragma unroll
            for (int j2 = 0; j2 < 2; j2++) {
                float2 kv = *(const float2*)&k_s[kk * 68 + 4 * tx + 2 * j2];
                b2[j2] = pack2(kv.x, kv.y);
            }
#pragma unroll
            for (int i = 0; i < 4; i++)
#pragma unroll
                for (int j2 = 0; j2 < 2; j2++) fma2(sa[i][j2], a2[i], b2[j2]);
        }

#pragma unroll
        for (int i = 0; i < 4; i++) {
            int n = n0 + 4 * ty + i;
            int nc = (n < Nn) ? n : 0;
            const float* brow = biasb + nc * Nn + m0 + 4 * tx;
            float bias4[4];
            if (m0 + 4 * tx + 3 < Nn) {
                float4 bv = *(const float4*)brow;
                bias4[0] = bv.x; bias4[1] = bv.y; bias4[2] = bv.z; bias4[3] = bv.w;
            } else {
#pragma unroll
                for (int jj = 0; jj < 4; jj++) {
                    int m = m0 + 4 * tx + jj;
                    bias4[jj] = (m < Nn) ? brow[jj] : 0.f;
                }
            }
#pragma unroll
            for (int j2 = 0; j2 < 2; j2++) {
                float2 sv = unpack2(sa[i][j2]);
                int mA = m0 + 4 * tx + 2 * j2;
                float p0 = (mA     < Nn) ? __expf(sv.x * SCALE + bias4[2 * j2 + 0]) : 0.f;
                float p1 = (mA + 1 < Nn) ? __expf(sv.y * SCALE + bias4[2 * j2 + 1]) : 0.f;
                p_s[(4 * tx + 2 * j2 + 0) * 69 + 4 * ty + i] = p0;
                p_s[(4 * tx + 2 * j2 + 1) * 69 + 4 * ty + i] = p1;
                rsum[i] += p0 + p1;
            }
        }
        __syncthreads();

#pragma unroll 8
        for (int j = 0; j < 64; j++) {
            unsigned long long pf[4], vf[4];
#pragma unroll
            for (int ii = 0; ii < 4; ii++) { float pv = p_s[j * 69 + 4 * ty + ii]; pf[ii] = pack2(pv, pv); }
#pragma unroll
            for (int c2 = 0; c2 < 4; c2++) {
                float2 vv = *(const float2*)&v_s[j * 128 + 2 * tx + 32 * c2];
                vf[c2] = pack2(vv.x, vv.y);
            }
#pragma unroll
            for (int ii = 0; ii < 4; ii++)
#pragma unroll
                for (int c2 = 0; c2 < 4; c2++) fma2(o_acc[ii][c2], pf[ii], vf[c2]);
        }
    }

#pragma unroll
    for (int i = 0; i < 4; i++)
#pragma unroll
        for (int off = 8; off > 0; off >>= 1)
            rsum[i] += __shfl_xor_sync(0xffffffffu, rsum[i], off, 16);

#pragma unroll
    for (int ii = 0; ii < 4; ii++) {
        int n = n0 + 4 * ty + ii;
        if (n >= Nn) continue;
        float inv = 1.f / rsum[ii];
#pragma unroll
        for (int c2 = 0; c2 < 4; c2++) {
            float2 ov = unpack2(o_acc[ii][c2]);
            float o0v = ov.x * inv, o1v = ov.y * inv;
            o0v = o0v * fminf(fmaxf(o0v + 3.f, 0.f), 6.f) * (1.f / 6.f);
            o1v = o1v * fminf(fmaxf(o1v + 3.f, 0.f), 6.f) * (1.f / 6.f);
            *(float2*)&g_o[(b * Nn + n) * VAL_ATTNc + h * VDc + 2 * tx + 32 * c2] =
                make_float2(o0v, o1v);
        }
    }
}

// ---------------- launch ----------------
extern "C" void kernel_launch(void* const* d_in, const int* in_sizes, int n_in,
                              void* d_out, int out_size) {
    (void)in_sizes; (void)n_in; (void)out_size;
    const float* x      = (const float*)d_in[0];
    const float* qkv_w  = (const float*)d_in[1];
    const float* qkv_g  = (const float*)d_in[2];
    const float* qkv_b  = (const float*)d_in[3];
    const float* qkv_m  = (const float*)d_in[4];
    const float* qkv_v  = (const float*)d_in[5];
    const float* ab     = (const float*)d_in[6];
    const float* proj_w = (const float*)d_in[7];
    const float* proj_g = (const float*)d_in[8];
    const float* proj_b = (const float*)d_in[9];
    const float* proj_m = (const float*)d_in[10];
    const float* proj_v = (const float*)d_in[11];
    const int*   idxs   = (const int*)d_in[12];
    float* out = (float*)d_out;

    bn_coef_kernel<<<6, 256>>>(qkv_g, qkv_b, qkv_m, qkv_v, proj_g, proj_b, proj_m, proj_v);
    bias_kernel<<<(Nn * Nn + 255) / 256, 256>>>(ab, idxs);

    cvt_hilo_kernel<<<(Bc * Nn * DIMc / 4 + 255) / 256, 256>>>(x, 0, Bc * Nn * DIMc / 4);
    cvt_hilo_kernel<<<(QKV_OUTc * DIMc / 4 + 255) / 256, 256>>>(qkv_w, 1, QKV_OUTc * DIMc / 4);
    cvt_hilo_kernel<<<(DIMc * VAL_ATTNc / 4 + 255) / 256, 256>>>(proj_w, 3, DIMc * VAL_ATTNc / 4);

    mma_gemm_kernel<<<dim3(196, 12), 256>>>(0, nullptr);   // QKV: K=512, N=1536

    const int ATTN_SMEM = (32 * 68 * 2 + 64 * 128 + 64 * 69) * 4;  // 67840 B
    cudaFuncSetAttribute(attn_kernel, cudaFuncAttributeMaxDynamicSharedMemorySize, ATTN_SMEM);
    attn_kernel<<<dim3(13, 8, 32), 256, ATTN_SMEM>>>();

    cvt_hilo_kernel<<<(Bc * Nn * VAL_ATTNc / 4 + 255) / 256, 256>>>(nullptr, 2, Bc * Nn * VAL_ATTNc / 4);
    mma_gemm_kernel<<<dim3(196, 4), 256>>>(1, out);        // proj: K=1024, N=512
}

// round 8
// speedup vs baseline: 2.2703x; 1.4937x over previous
#include <cuda_runtime.h>
#include <cuda_bf16.h>
#include <math.h>
#include <cstdint>

#define Bc 32
#define Nn 784
#define DIMc 512
#define Hh 8
#define KDc 32
#define VDc 128
#define QKV_OUTc 1536
#define VAL_ATTNc 1024
#define SCALE 0.17677669529663687f
#define LOG2E 1.4426950408889634f

// ---------------- scratch (static device globals) ----------------
__device__ float g_v[Bc * Hh * Nn * VDc];          // [bh][n][128] fp32
__device__ float g_o[Bc * Nn * VAL_ATTNc];         // [b][n][h*128+d]
__device__ float g_bias[Hh * Nn * Nn];             // [h][n][m]
__device__ float g_qs[QKV_OUTc], g_qbb[QKV_OUTc];
__device__ float g_ps[DIMc], g_pbb[DIMc];

// split-bf16 buffers
__device__ __nv_bfloat16 g_qh[Bc * Hh * Nn * KDc], g_ql[Bc * Hh * Nn * KDc];   // [bh][n][32]
__device__ __nv_bfloat16 g_kh[Bc * Hh * Nn * KDc], g_kl[Bc * Hh * Nn * KDc];
__device__ __nv_bfloat16 g_vth[Bc * Hh * VDc * Nn], g_vtl[Bc * Hh * VDc * Nn]; // [bh][d][n]
__device__ __nv_bfloat16 g_xh[Bc * Nn * DIMc],  g_xl[Bc * Nn * DIMc];
__device__ __nv_bfloat16 g_wqh[QKV_OUTc * DIMc], g_wql[QKV_OUTc * DIMc];
__device__ __nv_bfloat16 g_oh[Bc * Nn * VAL_ATTNc], g_ol[Bc * Nn * VAL_ATTNc];
__device__ __nv_bfloat16 g_wph[DIMc * VAL_ATTNc], g_wpl[DIMc * VAL_ATTNc];

// ---------------- helpers ----------------
static __device__ __forceinline__ unsigned pk_bf(__nv_bfloat16 a, __nv_bfloat16 b) {
    return ((unsigned)__bfloat16_as_ushort(b) << 16) | (unsigned)__bfloat16_as_ushort(a);
}
static __device__ __forceinline__ unsigned pk_f2(float a, float b) {
    return pk_bf(__float2bfloat16(a), __float2bfloat16(b));
}
static __device__ __forceinline__ void mma_bf16(float* d, const unsigned* a, const unsigned* b) {
    asm("mma.sync.aligned.m16n8k16.row.col.f32.bf16.bf16.f32 "
        "{%0,%1,%2,%3}, {%4,%5,%6,%7}, {%8,%9}, {%0,%1,%2,%3};"
        : "+f"(d[0]), "+f"(d[1]), "+f"(d[2]), "+f"(d[3])
        : "r"(a[0]), "r"(a[1]), "r"(a[2]), "r"(a[3]), "r"(b[0]), "r"(b[1]));
}
// fast 2^t on fma/alu pipes (MUFU is the hidden softmax bottleneck: rt=8/SMSP)
static __device__ __forceinline__ float exp2_fast(float t) {
    t = fminf(fmaxf(t, -120.f), 120.f);
    float r = t + 12582912.f;                       // round-to-nearest-int trick
    int n = __float_as_int(r) - 0x4B400000;
    float f = t - (r - 12582912.f);                 // f in [-0.5, 0.5]
    float g = f * 0.6931471805599453f;
    float p = fmaf(g, 0.0083333333f, 0.0416666667f);
    p = fmaf(p, g, 0.1666666667f);
    p = fmaf(p, g, 0.5f);
    p = fmaf(p, g, 1.0f);
    p = fmaf(p, g, 1.0f);
    return __int_as_float(__float_as_int(p) + (n << 23));
}

// ---------------- BN coefficient folding ----------------
__global__ void bn_coef_kernel(const float* __restrict__ qg, const float* __restrict__ qb,
                               const float* __restrict__ qm, const float* __restrict__ qv,
                               const float* __restrict__ pg, const float* __restrict__ pb,
                               const float* __restrict__ pm, const float* __restrict__ pv) {
    int i = blockIdx.x * 256 + threadIdx.x;
    if (i < QKV_OUTc) {
        float s = qg[i] * rsqrtf(qv[i] + 1e-5f);
        g_qs[i] = s;
        g_qbb[i] = qb[i] - qm[i] * s;
    }
    if (i < DIMc) {
        float s = pg[i] * rsqrtf(pv[i] + 1e-5f);
        g_ps[i] = s;
        g_pbb[i] = pb[i] - pm[i] * s;
    }
}

// ---------------- bias gather ----------------
__global__ void bias_kernel(const float* __restrict__ ab, const int* __restrict__ idxs) {
    int nm = blockIdx.x * 256 + threadIdx.x;
    if (nm < Nn * Nn) {
        int idx = idxs[nm];
#pragma unroll
        for (int h = 0; h < Hh; h++)
            g_bias[h * Nn * Nn + nm] = ab[h * Nn + idx];
    }
}

// ---------------- fp32 -> hi/lo bf16 conversion ----------------
__global__ void cvt_hilo_kernel(const float* __restrict__ s, int which, int n4) {
    int i = blockIdx.x * 256 + threadIdx.x;
    if (i >= n4) return;
    const float4* sp;
    __nv_bfloat16 *h, *l;
    if (which == 0)      { sp = (const float4*)s;   h = g_xh;  l = g_xl;  }
    else if (which == 1) { sp = (const float4*)s;   h = g_wqh; l = g_wql; }
    else if (which == 2) { sp = (const float4*)g_o; h = g_oh;  l = g_ol;  }
    else                 { sp = (const float4*)s;   h = g_wph; l = g_wpl; }
    float4 v = sp[i];
    __nv_bfloat16 h0 = __float2bfloat16(v.x), h1 = __float2bfloat16(v.y);
    __nv_bfloat16 h2 = __float2bfloat16(v.z), h3 = __float2bfloat16(v.w);
    __nv_bfloat16 l0 = __float2bfloat16(v.x - __bfloat162float(h0));
    __nv_bfloat16 l1 = __float2bfloat16(v.y - __bfloat162float(h1));
    __nv_bfloat16 l2 = __float2bfloat16(v.z - __bfloat162float(h2));
    __nv_bfloat16 l3 = __float2bfloat16(v.w - __bfloat162float(h3));
    ((uint2*)h)[i] = make_uint2(pk_bf(h0, h1), pk_bf(h2, h3));
    ((uint2*)l)[i] = make_uint2(pk_bf(l0, l1), pk_bf(l2, l3));
}

// ---------------- V transpose + split: g_v[bh][n][d] -> g_vt{h,l}[bh][d][n] ----------------
__global__ __launch_bounds__(256) void vtrans_kernel() {
    __shared__ float Ts[64][65];
    int bh = blockIdx.x, n0 = blockIdx.y * 64, d0 = blockIdx.z * 64;
    int t = threadIdx.x;
#pragma unroll
    for (int e = t; e < 4096; e += 256) {
        int r = e >> 6, c = e & 63;
        Ts[r][c] = (n0 + r < Nn) ? g_v[((size_t)(bh * Nn) + n0 + r) * VDc + d0 + c] : 0.f;
    }
    __syncthreads();
#pragma unroll
    for (int e = t; e < 2048; e += 256) {
        int d = e >> 5, kp = e & 31;
        int n = n0 + 2 * kp;
        if (n < Nn) {
            float v0 = Ts[2 * kp][d], v1 = Ts[2 * kp + 1][d];
            __nv_bfloat16 h0 = __float2bfloat16(v0), h1 = __float2bfloat16(v1);
            size_t idx = ((size_t)(bh * VDc) + d0 + d) * Nn + n;
            *(unsigned*)&g_vth[idx] = pk_bf(h0, h1);
            *(unsigned*)&g_vtl[idx] = pk_bf(__float2bfloat16(v0 - __bfloat162float(h0)),
                                            __float2bfloat16(v1 - __bfloat162float(h1)));
        }
    }
}

// ---------------- qkv scatter: q,k -> packed split-bf16; v -> fp32 ----------------
static __device__ __forceinline__ void qkv_scatter2(int b, int n, int o, float y0, float y1) {
    int h = o / 192, r = o - h * 192;
    int bh = b * Hh + h;
    if (r < 2 * KDc) {
        __nv_bfloat16 h0 = __float2bfloat16(y0), h1 = __float2bfloat16(y1);
        unsigned hi = pk_bf(h0, h1);
        unsigned lo = pk_bf(__float2bfloat16(y0 - __bfloat162float(h0)),
                            __float2bfloat16(y1 - __bfloat162float(h1)));
        if (r < KDc) {
            size_t idx = ((size_t)(bh * Nn) + n) * KDc + r;
            *(unsigned*)&g_qh[idx] = hi; *(unsigned*)&g_ql[idx] = lo;
        } else {
            size_t idx = ((size_t)(bh * Nn) + n) * KDc + (r - KDc);
            *(unsigned*)&g_kh[idx] = hi; *(unsigned*)&g_kl[idx] = lo;
        }
    } else {
        size_t idx = ((size_t)(bh * Nn) + n) * VDc + (r - 2 * KDc);
        g_v[idx] = y0; g_v[idx + 1] = y1;
    }
}

// ---------------- split-bf16 mma.sync GEMM (from R7, epilogue updated) ----------------
#define SSTR 40
__global__ __launch_bounds__(256, 2) void mma_gemm_kernel(int mode, float* __restrict__ out) {
    __shared__ __align__(16) __nv_bfloat16 Ah_s[128 * SSTR];
    __shared__ __align__(16) __nv_bfloat16 Al_s[128 * SSTR];
    __shared__ __align__(16) __nv_bfloat16 Bh_s[128 * SSTR];
    __shared__ __align__(16) __nv_bfloat16 Bl_s[128 * SSTR];

    int t = threadIdx.x;
    int lane = t & 31, wid = t >> 5;
    int g = lane >> 2, tg = lane & 3;
    int warp_m = wid >> 2, warp_n = wid & 3;
    int m0 = blockIdx.x * 128, o0 = blockIdx.y * 128;

    const __nv_bfloat16 *Ah, *Al, *Bh, *Bl;
    int K;
    if (mode == 0) { Ah = g_xh; Al = g_xl; Bh = g_wqh; Bl = g_wql; K = DIMc; }
    else           { Ah = g_oh; Al = g_ol; Bh = g_wph; Bl = g_wpl; K = VAL_ATTNc; }

    float acc[4][4][4];
#pragma unroll
    for (int i = 0; i < 4; i++)
#pragma unroll
        for (int j = 0; j < 4; j++)
#pragma unroll
            for (int c = 0; c < 4; c++) acc[i][j][c] = 0.f;

    for (int k0 = 0; k0 < K; k0 += 32) {
#pragma unroll
        for (int ii = 0; ii < 2; ii++) {
            int e = t + 256 * ii;
            int r = e >> 2, c = e & 3;
            size_t ga = (size_t)(m0 + r) * K + k0 + 8 * c;
            size_t gb = (size_t)(o0 + r) * K + k0 + 8 * c;
            int so = r * SSTR + 8 * c;
            *(uint4*)&Ah_s[so] = *(const uint4*)&Ah[ga];
            *(uint4*)&Al_s[so] = *(const uint4*)&Al[ga];
            *(uint4*)&Bh_s[so] = *(const uint4*)&Bh[gb];
            *(uint4*)&Bl_s[so] = *(const uint4*)&Bl[gb];
        }
        __syncthreads();
#pragma unroll
        for (int kk = 0; kk < 2; kk++) {
            int kb = kk * 16 + 2 * tg;
            unsigned ah[4][4], al[4][4], bh[4][2], bl[4][2];
#pragma unroll
            for (int mi = 0; mi < 4; mi++) {
                int r0 = warp_m * 64 + mi * 16 + g;
                ah[mi][0] = *(const unsigned*)&Ah_s[r0 * SSTR + kb];
                ah[mi][1] = *(const unsigned*)&Ah_s[(r0 + 8) * SSTR + kb];
                ah[mi][2] = *(const unsigned*)&Ah_s[r0 * SSTR + kb + 8];
                ah[mi][3] = *(const unsigned*)&Ah_s[(r0 + 8) * SSTR + kb + 8];
                al[mi][0] = *(const unsigned*)&Al_s[r0 * SSTR + kb];
                al[mi][1] = *(const unsigned*)&Al_s[(r0 + 8) * SSTR + kb];
                al[mi][2] = *(const unsigned*)&Al_s[r0 * SSTR + kb + 8];
                al[mi][3] = *(const unsigned*)&Al_s[(r0 + 8) * SSTR + kb + 8];
            }
#pragma unroll
            for (int nj = 0; nj < 4; nj++) {
                int n = warp_n * 32 + nj * 8 + g;
                bh[nj][0] = *(const unsigned*)&Bh_s[n * SSTR + kb];
                bh[nj][1] = *(const unsigned*)&Bh_s[n * SSTR + kb + 8];
                bl[nj][0] = *(const unsigned*)&Bl_s[n * SSTR + kb];
                bl[nj][1] = *(const unsigned*)&Bl_s[n * SSTR + kb + 8];
            }
#pragma unroll
            for (int mi = 0; mi < 4; mi++)
#pragma unroll
                for (int nj = 0; nj < 4; nj++) {
                    mma_bf16(acc[mi][nj], ah[mi], bh[nj]);
                    mma_bf16(acc[mi][nj], ah[mi], bl[nj]);
                    mma_bf16(acc[mi][nj], al[mi], bh[nj]);
                }
        }
        __syncthreads();
    }

#pragma unroll
    for (int mi = 0; mi < 4; mi++) {
        int m_lo = m0 + warp_m * 64 + mi * 16 + g;
        int m_hi = m_lo + 8;
        if (mode == 0) {
            int b0 = m_lo / Nn, n0q = m_lo - b0 * Nn;
            int b1 = m_hi / Nn, n1q = m_hi - b1 * Nn;
#pragma unroll
            for (int nj = 0; nj < 4; nj++) {
                int o = o0 + warp_n * 32 + nj * 8 + 2 * tg;
                qkv_scatter2(b0, n0q, o, acc[mi][nj][0] * g_qs[o] + g_qbb[o],
                                         acc[mi][nj][1] * g_qs[o + 1] + g_qbb[o + 1]);
                qkv_scatter2(b1, n1q, o, acc[mi][nj][2] * g_qs[o] + g_qbb[o],
                                         acc[mi][nj][3] * g_qs[o + 1] + g_qbb[o + 1]);
            }
        } else {
#pragma unroll
            for (int nj = 0; nj < 4; nj++) {
                int o = o0 + warp_n * 32 + nj * 8 + 2 * tg;
                float s0 = g_ps[o], s1 = g_ps[o + 1];
                float c0 = g_pbb[o], c1 = g_pbb[o + 1];
                *(float2*)&out[(size_t)m_lo * DIMc + o] =
                    make_float2(acc[mi][nj][0] * s0 + c0, acc[mi][nj][1] * s1 + c1);
                *(float2*)&out[(size_t)m_hi * DIMc + o] =
                    make_float2(acc[mi][nj][2] * s0 + c0, acc[mi][nj][3] * s1 + c1);
            }
        }
    }
}

// ---------------- tensor-core attention ----------------
// 128 q-rows per CTA, 8 warps x 16 rows. Split-bf16 QK and PV (3 mma each).
// P accumulator layout == A-fragment layout (register reuse, no smem round-trip).
// smem bytes: Qh 10240 | Ql 10240 | Kh 5120 | Kl 5120 | Vth 18432 | Vtl 18432 = 67584
#define AQ_H 0
#define AQ_L 10240
#define AK_H 20480
#define AK_L 25600
#define AV_H 30720
#define AV_L 49152
#define ATTN_SMEM_B 67584
#define VSTR 72

__global__ __launch_bounds__(256) void attn_mma_kernel() {
    extern __shared__ char smc[];
    __nv_bfloat16* Qh_s = (__nv_bfloat16*)(smc + AQ_H);
    __nv_bfloat16* Ql_s = (__nv_bfloat16*)(smc + AQ_L);
    __nv_bfloat16* Kh_s = (__nv_bfloat16*)(smc + AK_H);
    __nv_bfloat16* Kl_s = (__nv_bfloat16*)(smc + AK_L);
    __nv_bfloat16* Vh_s = (__nv_bfloat16*)(smc + AV_H);
    __nv_bfloat16* Vl_s = (__nv_bfloat16*)(smc + AV_L);

    int n0q = blockIdx.x * 128;
    int h = blockIdx.y, b = blockIdx.z;
    int bh = b * Hh + h;
    int t = threadIdx.x, w = t >> 5, lane = t & 31;
    int g = lane >> 2, tg = lane & 3;

    const __nv_bfloat16* qhB = g_qh + (size_t)(bh * Nn) * KDc;
    const __nv_bfloat16* qlB = g_ql + (size_t)(bh * Nn) * KDc;
    const __nv_bfloat16* khB = g_kh + (size_t)(bh * Nn) * KDc;
    const __nv_bfloat16* klB = g_kl + (size_t)(bh * Nn) * KDc;
    const __nv_bfloat16* vhB = g_vth + (size_t)(bh * VDc) * Nn;
    const __nv_bfloat16* vlB = g_vtl + (size_t)(bh * VDc) * Nn;
    const float* biasb = g_bias + (size_t)h * Nn * Nn;

    // load Q tile (128 x 32), rows clamped at boundary
#pragma unroll
    for (int e = t; e < 512; e += 256) {
        int r = e >> 2, c = e & 3;
        int n = n0q + r; if (n >= Nn) n = Nn - 1;
        *(uint4*)&Qh_s[r * SSTR + 8 * c] = *(const uint4*)&qhB[(size_t)n * KDc + 8 * c];
        *(uint4*)&Ql_s[r * SSTR + 8 * c] = *(const uint4*)&qlB[(size_t)n * KDc + 8 * c];
    }

    float o_acc[16][4];
#pragma unroll
    for (int on = 0; on < 16; on++)
#pragma unroll
        for (int c = 0; c < 4; c++) o_acc[on][c] = 0.f;
    float rs0 = 0.f, rs1 = 0.f;

    int row0 = n0q + 16 * w + g;
    int nc0 = (row0 < Nn) ? row0 : (Nn - 1);
    int nc1 = (row0 + 8 < Nn) ? (row0 + 8) : (Nn - 1);

    for (int m0 = 0; m0 < Nn; m0 += 64) {
        __syncthreads();
        // K tile 64x32 hi/lo
        {
            int e = t;
            int r = e >> 2, c = e & 3;
            int m = m0 + r;
            if (m < Nn) {
                *(uint4*)&Kh_s[r * SSTR + 8 * c] = *(const uint4*)&khB[(size_t)m * KDc + 8 * c];
                *(uint4*)&Kl_s[r * SSTR + 8 * c] = *(const uint4*)&klB[(size_t)m * KDc + 8 * c];
            } else {
                *(uint4*)&Kh_s[r * SSTR + 8 * c] = make_uint4(0, 0, 0, 0);
                *(uint4*)&Kl_s[r * SSTR + 8 * c] = make_uint4(0, 0, 0, 0);
            }
        }
        // V^T tile 128 x 64 hi/lo
#pragma unroll
        for (int e = t; e < 2048; e += 256) {
            int r = e >> 4, c = e & 15;
            int m = m0 + 4 * c;
            if (m < Nn) {
                *(uint2*)&Vh_s[r * VSTR + 4 * c] = *(const uint2*)&vhB[(size_t)r * Nn + m];
                *(uint2*)&Vl_s[r * VSTR + 4 * c] = *(const uint2*)&vlB[(size_t)r * Nn + m];
            } else {
                *(uint2*)&Vh_s[r * VSTR + 4 * c] = make_uint2(0, 0);
                *(uint2*)&Vl_s[r * VSTR + 4 * c] = make_uint2(0, 0);
            }
        }
        __syncthreads();

        // ---- S = Q K^T (warp: 16 rows x 64 keys, k=32, split = 3 products) ----
        float sa[8][4];
#pragma unroll
        for (int nt = 0; nt < 8; nt++)
#pragma unroll
            for (int c = 0; c < 4; c++) sa[nt][c] = 0.f;
#pragma unroll
        for (int kt = 0; kt < 2; kt++) {
            unsigned ah[4], al[4];
            int qo = (16 * w + g) * SSTR + 16 * kt + 2 * tg;
            ah[0] = *(const unsigned*)&Qh_s[qo];
            ah[1] = *(const unsigned*)&Qh_s[qo + 8 * SSTR];
            ah[2] = *(const unsigned*)&Qh_s[qo + 8];
            ah[3] = *(const unsigned*)&Qh_s[qo + 8 * SSTR + 8];
            al[0] = *(const unsigned*)&Ql_s[qo];
            al[1] = *(const unsigned*)&Ql_s[qo + 8 * SSTR];
            al[2] = *(const unsigned*)&Ql_s[qo + 8];
            al[3] = *(const unsigned*)&Ql_s[qo + 8 * SSTR + 8];
#pragma unroll
            for (int nt = 0; nt < 8; nt++) {
                unsigned bh[2], bl[2];
                int ko = (8 * nt + g) * SSTR + 16 * kt + 2 * tg;
                bh[0] = *(const unsigned*)&Kh_s[ko];
                bh[1] = *(const unsigned*)&Kh_s[ko + 8];
                bl[0] = *(const unsigned*)&Kl_s[ko];
                bl[1] = *(const unsigned*)&Kl_s[ko + 8];
                mma_bf16(sa[nt], ah, bh);
                mma_bf16(sa[nt], ah, bl);
                mma_bf16(sa[nt], al, bh);
            }
        }

        // ---- bias + exp (poly, fma-pipe) -> P frags in registers ----
        unsigned ph[4][4], pl[4][4];
#pragma unroll
        for (int nt = 0; nt < 8; nt++) {
            int mcol = m0 + 8 * nt + 2 * tg;
            float2 bb0, bb1;
            if (mcol < Nn) {
                bb0 = *(const float2*)&biasb[(size_t)nc0 * Nn + mcol];
                bb1 = *(const float2*)&biasb[(size_t)nc1 * Nn + mcol];
            } else {
                bb0 = make_float2(-21000.f, -21000.f);
                bb1 = bb0;
            }
            float p0 = exp2_fast(fmaf(sa[nt][0], SCALE * LOG2E, bb0.x * LOG2E));
            float p1 = exp2_fast(fmaf(sa[nt][1], SCALE * LOG2E, bb0.y * LOG2E));
            float p2 = exp2_fast(fmaf(sa[nt][2], SCALE * LOG2E, bb1.x * LOG2E));
            float p3 = exp2_fast(fmaf(sa[nt][3], SCALE * LOG2E, bb1.y * LOG2E));
            rs0 += p0 + p1;
            rs1 += p2 + p3;
            // split to hi/lo bf16 A-fragments
            __nv_bfloat16 h0 = __float2bfloat16(p0), h1 = __float2bfloat16(p1);
            __nv_bfloat16 h2 = __float2bfloat16(p2), h3 = __float2bfloat16(p3);
            unsigned uh0 = pk_bf(h0, h1), uh1 = pk_bf(h2, h3);
            unsigned ul0 = pk_f2(p0 - __bfloat162float(h0), p1 - __bfloat162float(h1));
            unsigned ul1 = pk_f2(p2 - __bfloat162float(h2), p3 - __bfloat162float(h3));
            int kv = nt >> 1;
            if ((nt & 1) == 0) {
                ph[kv][0] = uh0; ph[kv][1] = uh1;
                pl[kv][0] = ul0; pl[kv][1] = ul1;
            } else {
                ph[kv][2] = uh0; ph[kv][3] = uh1;
                pl[kv][2] = ul0; pl[kv][3] = ul1;
            }
        }

        // ---- O += P V (warp: 16 rows x 128 cols, k=64, split = 3 products) ----
#pragma unroll
        for (int kv = 0; kv < 4; kv++) {
#pragma unroll
            for (int on = 0; on < 16; on++) {
                unsigned bh[2], bl[2];
                int vo = (8 * on + g) * VSTR + 16 * kv + 2 * tg;
                bh[0] = *(const unsigned*)&Vh_s[vo];
                bh[1] = *(const unsigned*)&Vh_s[vo + 8];
                bl[0] = *(const unsigned*)&Vl_s[vo];
                bl[1] = *(const unsigned*)&Vl_s[vo + 8];
                mma_bf16(o_acc[on], ph[kv], bh);
                mma_bf16(o_acc[on], ph[kv], bl);
                mma_bf16(o_acc[on], pl[kv], bh);
            }
        }
    }

    // reduce row sums across the 4 tg lanes of each group
    rs0 += __shfl_xor_sync(0xffffffffu, rs0, 1);
    rs0 += __shfl_xor_sync(0xffffffffu, rs0, 2);
    rs1 += __shfl_xor_sync(0xffffffffu, rs1, 1);
    rs1 += __shfl_xor_sync(0xffffffffu, rs1, 2);
    float inv0 = 1.f / rs0, inv1 = 1.f / rs1;

    // normalize + hardswish + store
    int nlo = n0q + 16 * w + g, nhi = nlo + 8;
#pragma unroll
    for (int on = 0; on < 16; on++) {
        int d = h * VDc + 8 * on + 2 * tg;
        if (nlo < Nn) {
            float a0 = o_acc[on][0] * inv0, a1 = o_acc[on][1] * inv0;
            a0 = a0 * fminf(fmaxf(a0 + 3.f, 0.f), 6.f) * (1.f / 6.f);
            a1 = a1 * fminf(fmaxf(a1 + 3.f, 0.f), 6.f) * (1.f / 6.f);
            *(float2*)&g_o[((size_t)b * Nn + nlo) * VAL_ATTNc + d] = make_float2(a0, a1);
        }
        if (nhi < Nn) {
            float a2 = o_acc[on][2] * inv1, a3 = o_acc[on][3] * inv1;
            a2 = a2 * fminf(fmaxf(a2 + 3.f, 0.f), 6.f) * (1.f / 6.f);
            a3 = a3 * fminf(fmaxf(a3 + 3.f, 0.f), 6.f) * (1.f / 6.f);
            *(float2*)&g_o[((size_t)b * Nn + nhi) * VAL_ATTNc + d] = make_float2(a2, a3);
        }
    }
}

// ---------------- launch ----------------
extern "C" void kernel_launch(void* const* d_in, const int* in_sizes, int n_in,
                              void* d_out, int out_size) {
    (void)in_sizes; (void)n_in; (void)out_size;
    const float* x      = (const float*)d_in[0];
    const float* qkv_w  = (const float*)d_in[1];
    const float* qkv_g  = (const float*)d_in[2];
    const float* qkv_b  = (const float*)d_in[3];
    const float* qkv_m  = (const float*)d_in[4];
    const float* qkv_v  = (const float*)d_in[5];
    const float* ab     = (const float*)d_in[6];
    const float* proj_w = (const float*)d_in[7];
    const float* proj_g = (const float*)d_in[8];
    const float* proj_b = (const float*)d_in[9];
    const float* proj_m = (const float*)d_in[10];
    const float* proj_v = (const float*)d_in[11];
    const int*   idxs   = (const int*)d_in[12];
    float* out = (float*)d_out;

    bn_coef_kernel<<<6, 256>>>(qkv_g, qkv_b, qkv_m, qkv_v, proj_g, proj_b, proj_m, proj_v);
    bias_kernel<<<(Nn * Nn + 255) / 256, 256>>>(ab, idxs);

    cvt_hilo_kernel<<<(Bc * Nn * DIMc / 4 + 255) / 256, 256>>>(x, 0, Bc * Nn * DIMc / 4);
    cvt_hilo_kernel<<<(QKV_OUTc * DIMc / 4 + 255) / 256, 256>>>(qkv_w, 1, QKV_OUTc * DIMc / 4);
    cvt_hilo_kernel<<<(DIMc * VAL_ATTNc / 4 + 255) / 256, 256>>>(proj_w, 3, DIMc * VAL_ATTNc / 4);

    mma_gemm_kernel<<<dim3(196, 12), 256>>>(0, nullptr);   // QKV

    vtrans_kernel<<<dim3(Bc * Hh, 13, 2), 256>>>();        // V -> V^T split-bf16

    cudaFuncSetAttribute(attn_mma_kernel, cudaFuncAttributeMaxDynamicSharedMemorySize, ATTN_SMEM_B);
    attn_mma_kernel<<<dim3(7, Hh, Bc), 256, ATTN_SMEM_B>>>();

    cvt_hilo_kernel<<<(Bc * Nn * VAL_ATTNc / 4 + 255) / 256, 256>>>(nullptr, 2, Bc * Nn * VAL_ATTNc / 4);
    mma_gemm_kernel<<<dim3(196, 4), 256>>>(1, out);        // proj
}

// round 9
// speedup vs baseline: 2.3968x; 1.0557x over previous
#include <cuda_runtime.h>
#include <cuda_bf16.h>
#include <math.h>
#include <cstdint>

#define Bc 32
#define Nn 784
#define DIMc 512
#define Hh 8
#define KDc 32
#define VDc 128
#define QKV_OUTc 1536
#define VAL_ATTNc 1024
#define SCALE 0.17677669529663687f
#define LOG2E 1.4426950408889634f

// ---------------- scratch (static device globals) ----------------
__device__ float g_v[Bc * Hh * Nn * VDc];          // [bh][n][128] fp32
__device__ float g_o[Bc * Nn * VAL_ATTNc];         // [b][n][h*128+d]
__device__ float g_bias[Hh * Nn * Nn];             // [h][n][m]
__device__ float g_qs[QKV_OUTc], g_qbb[QKV_OUTc];
__device__ float g_ps[DIMc], g_pbb[DIMc];

// split-bf16 buffers
__device__ __nv_bfloat16 g_qh[Bc * Hh * Nn * KDc], g_ql[Bc * Hh * Nn * KDc];   // [bh][n][32]
__device__ __nv_bfloat16 g_kh[Bc * Hh * Nn * KDc], g_kl[Bc * Hh * Nn * KDc];
__device__ __nv_bfloat16 g_vth[Bc * Hh * VDc * Nn], g_vtl[Bc * Hh * VDc * Nn]; // [bh][d][n]
__device__ __nv_bfloat16 g_xh[Bc * Nn * DIMc],  g_xl[Bc * Nn * DIMc];
__device__ __nv_bfloat16 g_wqh[QKV_OUTc * DIMc], g_wql[QKV_OUTc * DIMc];
__device__ __nv_bfloat16 g_oh[Bc * Nn * VAL_ATTNc], g_ol[Bc * Nn * VAL_ATTNc];
__device__ __nv_bfloat16 g_wph[DIMc * VAL_ATTNc], g_wpl[DIMc * VAL_ATTNc];

// ---------------- helpers ----------------
static __device__ __forceinline__ unsigned pk_bf(__nv_bfloat16 a, __nv_bfloat16 b) {
    return ((unsigned)__bfloat16_as_ushort(b) << 16) | (unsigned)__bfloat16_as_ushort(a);
}
static __device__ __forceinline__ unsigned pk_f2(float a, float b) {
    return pk_bf(__float2bfloat16(a), __float2bfloat16(b));
}
static __device__ __forceinline__ void mma_bf16(float* d, const unsigned* a, const unsigned* b) {
    asm("mma.sync.aligned.m16n8k16.row.col.f32.bf16.bf16.f32 "
        "{%0,%1,%2,%3}, {%4,%5,%6,%7}, {%8,%9}, {%0,%1,%2,%3};"
        : "+f"(d[0]), "+f"(d[1]), "+f"(d[2]), "+f"(d[3])
        : "r"(a[0]), "r"(a[1]), "r"(a[2]), "r"(a[3]), "r"(b[0]), "r"(b[1]));
}
static __device__ __forceinline__ uint32_t sm_u32(const void* p) {
    return (uint32_t)__cvta_generic_to_shared(p);
}
// ldmatrix x4: lane l supplies the row address of matrix (l>>3), row (l&7)
static __device__ __forceinline__ void ldsm4(unsigned* r, uint32_t a) {
    asm volatile("ldmatrix.sync.aligned.m8n8.x4.shared.b16 {%0,%1,%2,%3}, [%4];"
        : "=r"(r[0]), "=r"(r[1]), "=r"(r[2]), "=r"(r[3]) : "r"(a));
}
// fast 2^t on fma/alu pipes (MUFU rt=8 is the softmax bottleneck otherwise)
static __device__ __forceinline__ float exp2_fast(float t) {
    t = fminf(fmaxf(t, -120.f), 120.f);
    float r = t + 12582912.f;
    int n = __float_as_int(r) - 0x4B400000;
    float f = t - (r - 12582912.f);
    float g = f * 0.6931471805599453f;
    float p = fmaf(g, 0.0083333333f, 0.0416666667f);
    p = fmaf(p, g, 0.1666666667f);
    p = fmaf(p, g, 0.5f);
    p = fmaf(p, g, 1.0f);
    p = fmaf(p, g, 1.0f);
    return __int_as_float(__float_as_int(p) + (n << 23));
}

// ---------------- BN coefficient folding ----------------
__global__ void bn_coef_kernel(const float* __restrict__ qg, const float* __restrict__ qb,
                               const float* __restrict__ qm, const float* __restrict__ qv,
                               const float* __restrict__ pg, const float* __restrict__ pb,
                               const float* __restrict__ pm, const float* __restrict__ pv) {
    int i = blockIdx.x * 256 + threadIdx.x;
    if (i < QKV_OUTc) {
        float s = qg[i] * rsqrtf(qv[i] + 1e-5f);
        g_qs[i] = s;
        g_qbb[i] = qb[i] - qm[i] * s;
    }
    if (i < DIMc) {
        float s = pg[i] * rsqrtf(pv[i] + 1e-5f);
        g_ps[i] = s;
        g_pbb[i] = pb[i] - pm[i] * s;
    }
}

// ---------------- bias gather ----------------
__global__ void bias_kernel(const float* __restrict__ ab, const int* __restrict__ idxs) {
    int nm = blockIdx.x * 256 + threadIdx.x;
    if (nm < Nn * Nn) {
        int idx = idxs[nm];
#pragma unroll
        for (int h = 0; h < Hh; h++)
            g_bias[h * Nn * Nn + nm] = ab[h * Nn + idx];
    }
}

// ---------------- fp32 -> hi/lo bf16 conversion ----------------
__global__ void cvt_hilo_kernel(const float* __restrict__ s, int which, int n4) {
    int i = blockIdx.x * 256 + threadIdx.x;
    if (i >= n4) return;
    const float4* sp;
    __nv_bfloat16 *h, *l;
    if (which == 0)      { sp = (const float4*)s;   h = g_xh;  l = g_xl;  }
    else if (which == 1) { sp = (const float4*)s;   h = g_wqh; l = g_wql; }
    else if (which == 2) { sp = (const float4*)g_o; h = g_oh;  l = g_ol;  }
    else                 { sp = (const float4*)s;   h = g_wph; l = g_wpl; }
    float4 v = sp[i];
    __nv_bfloat16 h0 = __float2bfloat16(v.x), h1 = __float2bfloat16(v.y);
    __nv_bfloat16 h2 = __float2bfloat16(v.z), h3 = __float2bfloat16(v.w);
    __nv_bfloat16 l0 = __float2bfloat16(v.x - __bfloat162float(h0));
    __nv_bfloat16 l1 = __float2bfloat16(v.y - __bfloat162float(h1));
    __nv_bfloat16 l2 = __float2bfloat16(v.z - __bfloat162float(h2));
    __nv_bfloat16 l3 = __float2bfloat16(v.w - __bfloat162float(h3));
    ((uint2*)h)[i] = make_uint2(pk_bf(h0, h1), pk_bf(h2, h3));
    ((uint2*)l)[i] = make_uint2(pk_bf(l0, l1), pk_bf(l2, l3));
}

// ---------------- V transpose + split: g_v[bh][n][d] -> g_vt{h,l}[bh][d][n] ----------------
__global__ __launch_bounds__(256) void vtrans_kernel() {
    __shared__ float Ts[64][65];
    int bh = blockIdx.x, n0 = blockIdx.y * 64, d0 = blockIdx.z * 64;
    int t = threadIdx.x;
#pragma unroll
    for (int e = t; e < 4096; e += 256) {
        int r = e >> 6, c = e & 63;
        Ts[r][c] = (n0 + r < Nn) ? g_v[((size_t)(bh * Nn) + n0 + r) * VDc + d0 + c] : 0.f;
    }
    __syncthreads();
#pragma unroll
    for (int e = t; e < 2048; e += 256) {
        int d = e >> 5, kp = e & 31;
        int n = n0 + 2 * kp;
        if (n < Nn) {
            float v0 = Ts[2 * kp][d], v1 = Ts[2 * kp + 1][d];
            __nv_bfloat16 h0 = __float2bfloat16(v0), h1 = __float2bfloat16(v1);
            size_t idx = ((size_t)(bh * VDc) + d0 + d) * Nn + n;
            *(unsigned*)&g_vth[idx] = pk_bf(h0, h1);
            *(unsigned*)&g_vtl[idx] = pk_bf(__float2bfloat16(v0 - __bfloat162float(h0)),
                                            __float2bfloat16(v1 - __bfloat162float(h1)));
        }
    }
}

// ---------------- qkv scatter: q,k -> packed split-bf16; v -> fp32 ----------------
static __device__ __forceinline__ void qkv_scatter2(int b, int n, int o, float y0, float y1) {
    int h = o / 192, r = o - h * 192;
    int bh = b * Hh + h;
    if (r < 2 * KDc) {
        __nv_bfloat16 h0 = __float2bfloat16(y0), h1 = __float2bfloat16(y1);
        unsigned hi = pk_bf(h0, h1);
        unsigned lo = pk_bf(__float2bfloat16(y0 - __bfloat162float(h0)),
                            __float2bfloat16(y1 - __bfloat162float(h1)));
        if (r < KDc) {
            size_t idx = ((size_t)(bh * Nn) + n) * KDc + r;
            *(unsigned*)&g_qh[idx] = hi; *(unsigned*)&g_ql[idx] = lo;
        } else {
            size_t idx = ((size_t)(bh * Nn) + n) * KDc + (r - KDc);
            *(unsigned*)&g_kh[idx] = hi; *(unsigned*)&g_kl[idx] = lo;
        }
    } else {
        size_t idx = ((size_t)(bh * Nn) + n) * VDc + (r - 2 * KDc);
        g_v[idx] = y0; g_v[idx + 1] = y1;
    }
}

// ---------------- split-bf16 mma.sync GEMM with ldmatrix fragment loads ----------------
#define SSTR 40
__global__ __launch_bounds__(256, 2) void mma_gemm_kernel(int mode, float* __restrict__ out) {
    __shared__ __align__(16) __nv_bfloat16 Ah_s[128 * SSTR];
    __shared__ __align__(16) __nv_bfloat16 Al_s[128 * SSTR];
    __shared__ __align__(16) __nv_bfloat16 Bh_s[128 * SSTR];
    __shared__ __align__(16) __nv_bfloat16 Bl_s[128 * SSTR];

    int t = threadIdx.x;
    int lane = t & 31, wid = t >> 5;
    int g = lane >> 2, tg = lane & 3;
    int sub = lane >> 3, rr = lane & 7;
    int warp_m = wid >> 2, warp_n = wid & 3;
    int m0 = blockIdx.x * 128, o0 = blockIdx.y * 128;

    const __nv_bfloat16 *Ah, *Al, *Bh, *Bl;
    int K;
    if (mode == 0) { Ah = g_xh; Al = g_xl; Bh = g_wqh; Bl = g_wql; K = DIMc; }
    else           { Ah = g_oh; Al = g_ol; Bh = g_wph; Bl = g_wpl; K = VAL_ATTNc; }

    // ldmatrix per-lane base addresses
    // A x4: mats (m0,k0),(m8,k0),(m0,k8),(m8,k8): m_off=(sub&1)*8+rr, k_off=(sub>>1)*8
    uint32_t ah_base = sm_u32(Ah_s) +
        (uint32_t)(((warp_m * 64 + (sub & 1) * 8 + rr) * SSTR + (sub >> 1) * 8) * 2);
    uint32_t al_base = sm_u32(Al_s) +
        (uint32_t)(((warp_m * 64 + (sub & 1) * 8 + rr) * SSTR + (sub >> 1) * 8) * 2);
    // B x4 hi/lo fused: mats (hi,k0),(hi,k8),(lo,k0),(lo,k8)
    uint32_t b_base = sm_u32(sub < 2 ? Bh_s : Bl_s) +
        (uint32_t)(((warp_n * 32 + rr) * SSTR + (sub & 1) * 8) * 2);

    float acc[4][4][4];
#pragma unroll
    for (int i = 0; i < 4; i++)
#pragma unroll
        for (int j = 0; j < 4; j++)
#pragma unroll
            for (int c = 0; c < 4; c++) acc[i][j][c] = 0.f;

    for (int k0 = 0; k0 < K; k0 += 32) {
#pragma unroll
        for (int ii = 0; ii < 2; ii++) {
            int e = t + 256 * ii;
            int r = e >> 2, c = e & 3;
            size_t ga = (size_t)(m0 + r) * K + k0 + 8 * c;
            size_t gb = (size_t)(o0 + r) * K + k0 + 8 * c;
            int so = r * SSTR + 8 * c;
            *(uint4*)&Ah_s[so] = *(const uint4*)&Ah[ga];
            *(uint4*)&Al_s[so] = *(const uint4*)&Al[ga];
            *(uint4*)&Bh_s[so] = *(const uint4*)&Bh[gb];
            *(uint4*)&Bl_s[so] = *(const uint4*)&Bl[gb];
        }
        __syncthreads();
#pragma unroll
        for (int kk = 0; kk < 2; kk++) {
            unsigned ah[4][4], al[4][4], bb[4][4];
#pragma unroll
            for (int mi = 0; mi < 4; mi++) {
                uint32_t off = (uint32_t)((mi * 16 * SSTR + kk * 16) * 2);
                ldsm4(ah[mi], ah_base + off);
                ldsm4(al[mi], al_base + off);
            }
#pragma unroll
            for (int nj = 0; nj < 4; nj++)
                ldsm4(bb[nj], b_base + (uint32_t)((nj * 8 * SSTR + kk * 16) * 2));
#pragma unroll
            for (int mi = 0; mi < 4; mi++)
#pragma unroll
                for (int nj = 0; nj < 4; nj++) {
                    mma_bf16(acc[mi][nj], ah[mi], bb[nj]);      // hi*hi
                    mma_bf16(acc[mi][nj], ah[mi], bb[nj] + 2);  // hi*lo
                    mma_bf16(acc[mi][nj], al[mi], bb[nj]);      // lo*hi
                }
        }
        __syncthreads();
    }

#pragma unroll
    for (int mi = 0; mi < 4; mi++) {
        int m_lo = m0 + warp_m * 64 + mi * 16 + g;
        int m_hi = m_lo + 8;
        if (mode == 0) {
            int b0 = m_lo / Nn, n0q = m_lo - b0 * Nn;
            int b1 = m_hi / Nn, n1q = m_hi - b1 * Nn;
#pragma unroll
            for (int nj = 0; nj < 4; nj++) {
                int o = o0 + warp_n * 32 + nj * 8 + 2 * tg;
                qkv_scatter2(b0, n0q, o, acc[mi][nj][0] * g_qs[o] + g_qbb[o],
                                         acc[mi][nj][1] * g_qs[o + 1] + g_qbb[o + 1]);
                qkv_scatter2(b1, n1q, o, acc[mi][nj][2] * g_qs[o] + g_qbb[o],
                                         acc[mi][nj][3] * g_qs[o + 1] + g_qbb[o + 1]);
            }
        } else {
#pragma unroll
            for (int nj = 0; nj < 4; nj++) {
                int o = o0 + warp_n * 32 + nj * 8 + 2 * tg;
                float s0 = g_ps[o], s1 = g_ps[o + 1];
                float c0 = g_pbb[o], c1 = g_pbb[o + 1];
                *(float2*)&out[(size_t)m_lo * DIMc + o] =
                    make_float2(acc[mi][nj][0] * s0 + c0, acc[mi][nj][1] * s1 + c1);
                *(float2*)&out[(size_t)m_hi * DIMc + o] =
                    make_float2(acc[mi][nj][2] * s0 + c0, acc[mi][nj][3] * s1 + c1);
            }
        }
    }
}

// ---------------- tensor-core attention with ldmatrix fragment loads ----------------
#define AQ_H 0
#define AQ_L 10240
#define AK_H 20480
#define AK_L 25600
#define AV_H 30720
#define AV_L 49152
#define ATTN_SMEM_B 67584
#define VSTR 72

__global__ __launch_bounds__(256) void attn_mma_kernel() {
    extern __shared__ char smc[];
    __nv_bfloat16* Qh_s = (__nv_bfloat16*)(smc + AQ_H);
    __nv_bfloat16* Ql_s = (__nv_bfloat16*)(smc + AQ_L);
    __nv_bfloat16* Kh_s = (__nv_bfloat16*)(smc + AK_H);
    __nv_bfloat16* Kl_s = (__nv_bfloat16*)(smc + AK_L);
    __nv_bfloat16* Vh_s = (__nv_bfloat16*)(smc + AV_H);
    __nv_bfloat16* Vl_s = (__nv_bfloat16*)(smc + AV_L);

    int n0q = blockIdx.x * 128;
    int h = blockIdx.y, b = blockIdx.z;
    int bh = b * Hh + h;
    int t = threadIdx.x, w = t >> 5, lane = t & 31;
    int g = lane >> 2, tg = lane & 3;
    int sub = lane >> 3, rr = lane & 7;

    const __nv_bfloat16* qhB = g_qh + (size_t)(bh * Nn) * KDc;
    const __nv_bfloat16* qlB = g_ql + (size_t)(bh * Nn) * KDc;
    const __nv_bfloat16* khB = g_kh + (size_t)(bh * Nn) * KDc;
    const __nv_bfloat16* klB = g_kl + (size_t)(bh * Nn) * KDc;
    const __nv_bfloat16* vhB = g_vth + (size_t)(bh * VDc) * Nn;
    const __nv_bfloat16* vlB = g_vtl + (size_t)(bh * VDc) * Nn;
    const float* biasb = g_bias + (size_t)h * Nn * Nn;

    // ldmatrix per-lane base addresses
    uint32_t q_moff = (uint32_t)((16 * w + (sub & 1) * 8 + rr) * SSTR + (sub >> 1) * 8) * 2;
    uint32_t qh_base = sm_u32(Qh_s) + q_moff;
    uint32_t ql_base = sm_u32(Ql_s) + q_moff;
    uint32_t k_base = sm_u32(sub < 2 ? Kh_s : Kl_s) +
        (uint32_t)((rr * SSTR + (sub & 1) * 8) * 2);
    uint32_t v_base = sm_u32(sub < 2 ? Vh_s : Vl_s) +
        (uint32_t)((rr * VSTR + (sub & 1) * 8) * 2);

    // load Q tile (128 x 32), rows clamped at boundary
#pragma unroll
    for (int e = t; e < 512; e += 256) {
        int r = e >> 2, c = e & 3;
        int n = n0q + r; if (n >= Nn) n = Nn - 1;
        *(uint4*)&Qh_s[r * SSTR + 8 * c] = *(const uint4*)&qhB[(size_t)n * KDc + 8 * c];
        *(uint4*)&Ql_s[r * SSTR + 8 * c] = *(const uint4*)&qlB[(size_t)n * KDc + 8 * c];
    }

    float o_acc[16][4];
#pragma unroll
    for (int on = 0; on < 16; on++)
#pragma unroll
        for (int c = 0; c < 4; c++) o_acc[on][c] = 0.f;
    float rs0 = 0.f, rs1 = 0.f;

    int row0 = n0q + 16 * w + g;
    int nc0 = (row0 < Nn) ? row0 : (Nn - 1);
    int nc1 = (row0 + 8 < Nn) ? (row0 + 8) : (Nn - 1);

    for (int m0 = 0; m0 < Nn; m0 += 64) {
        __syncthreads();
        // K tile 64x32 hi/lo
        {
            int r = t >> 2, c = t & 3;
            int m = m0 + r;
            if (m < Nn) {
                *(uint4*)&Kh_s[r * SSTR + 8 * c] = *(const uint4*)&khB[(size_t)m * KDc + 8 * c];
                *(uint4*)&Kl_s[r * SSTR + 8 * c] = *(const uint4*)&klB[(size_t)m * KDc + 8 * c];
            } else {
                *(uint4*)&Kh_s[r * SSTR + 8 * c] = make_uint4(0, 0, 0, 0);
                *(uint4*)&Kl_s[r * SSTR + 8 * c] = make_uint4(0, 0, 0, 0);
            }
        }
        // V^T tile 128 x 64 hi/lo
#pragma unroll
        for (int e = t; e < 2048; e += 256) {
            int r = e >> 4, c = e & 15;
            int m = m0 + 4 * c;
            if (m < Nn) {
                *(uint2*)&Vh_s[r * VSTR + 4 * c] = *(const uint2*)&vhB[(size_t)r * Nn + m];
                *(uint2*)&Vl_s[r * VSTR + 4 * c] = *(const uint2*)&vlB[(size_t)r * Nn + m];
            } else {
                *(uint2*)&Vh_s[r * VSTR + 4 * c] = make_uint2(0, 0);
                *(uint2*)&Vl_s[r * VSTR + 4 * c] = make_uint2(0, 0);
            }
        }
        __syncthreads();

        // ---- S = Q K^T ----
        float sa[8][4];
#pragma unroll
        for (int nt = 0; nt < 8; nt++)
#pragma unroll
            for (int c = 0; c < 4; c++) sa[nt][c] = 0.f;
#pragma unroll
        for (int kt = 0; kt < 2; kt++) {
            unsigned ah[4], al[4];
            ldsm4(ah, qh_base + kt * 32);
            ldsm4(al, ql_base + kt * 32);
#pragma unroll
            for (int nt = 0; nt < 8; nt++) {
                unsigned bb[4];
                ldsm4(bb, k_base + (uint32_t)((nt * 8 * SSTR) * 2 + kt * 32));
                mma_bf16(sa[nt], ah, bb);
                mma_bf16(sa[nt], ah, bb + 2);
                mma_bf16(sa[nt], al, bb);
            }
        }

        // ---- bias + exp (poly) -> P frags in registers ----
        unsigned ph[4][4], pl[4][4];
#pragma unroll
        for (int nt = 0; nt < 8; nt++) {
            int mcol = m0 + 8 * nt + 2 * tg;
            float2 bb0, bb1;
            if (mcol < Nn) {
                bb0 = *(const float2*)&biasb[(size_t)nc0 * Nn + mcol];
                bb1 = *(const float2*)&biasb[(size_t)nc1 * Nn + mcol];
            } else {
                bb0 = make_float2(-21000.f, -21000.f);
                bb1 = bb0;
            }
            float p0 = exp2_fast(fmaf(sa[nt][0], SCALE * LOG2E, bb0.x * LOG2E));
            float p1 = exp2_fast(fmaf(sa[nt][1], SCALE * LOG2E, bb0.y * LOG2E));
            float p2 = exp2_fast(fmaf(sa[nt][2], SCALE * LOG2E, bb1.x * LOG2E));
            float p3 = exp2_fast(fmaf(sa[nt][3], SCALE * LOG2E, bb1.y * LOG2E));
            rs0 += p0 + p1;
            rs1 += p2 + p3;
            __nv_bfloat16 h0 = __float2bfloat16(p0), h1 = __float2bfloat16(p1);
            __nv_bfloat16 h2 = __float2bfloat16(p2), h3 = __float2bfloat16(p3);
            unsigned uh0 = pk_bf(h0, h1), uh1 = pk_bf(h2, h3);
            unsigned ul0 = pk_f2(p0 - __bfloat162float(h0), p1 - __bfloat162float(h1));
            unsigned ul1 = pk_f2(p2 - __bfloat162float(h2), p3 - __bfloat162float(h3));
            int kv = nt >> 1;
            if ((nt & 1) == 0) {
                ph[kv][0] = uh0; ph[kv][1] = uh1;
                pl[kv][0] = ul0; pl[kv][1] = ul1;
            } else {
                ph[kv][2] = uh0; ph[kv][3] = uh1;
                pl[kv][2] = ul0; pl[kv][3] = ul1;
            }
        }

        // ---- O += P V ----
#pragma unroll
        for (int kv = 0; kv < 4; kv++) {
#pragma unroll
            for (int on = 0; on < 16; on++) {
                unsigned bb[4];
                ldsm4(bb, v_base + (uint32_t)((on * 8 * VSTR) * 2 + kv * 32));
                mma_bf16(o_acc[on], ph[kv], bb);
                mma_bf16(o_acc[on], ph[kv], bb + 2);
                mma_bf16(o_acc[on], pl[kv], bb);
            }
        }
    }

    // reduce row sums across the 4 tg lanes of each group
    rs0 += __shfl_xor_sync(0xffffffffu, rs0, 1);
    rs0 += __shfl_xor_sync(0xffffffffu, rs0, 2);
    rs1 += __shfl_xor_sync(0xffffffffu, rs1, 1);
    rs1 += __shfl_xor_sync(0xffffffffu, rs1, 2);
    float inv0 = 1.f / rs0, inv1 = 1.f / rs1;

    // normalize + hardswish + store
    int nlo = n0q + 16 * w + g, nhi = nlo + 8;
#pragma unroll
    for (int on = 0; on < 16; on++) {
        int d = h * VDc + 8 * on + 2 * tg;
        if (nlo < Nn) {
            float a0 = o_acc[on][0] * inv0, a1 = o_acc[on][1] * inv0;
            a0 = a0 * fminf(fmaxf(a0 + 3.f, 0.f), 6.f) * (1.f / 6.f);
            a1 = a1 * fminf(fmaxf(a1 + 3.f, 0.f), 6.f) * (1.f / 6.f);
            *(float2*)&g_o[((size_t)b * Nn + nlo) * VAL_ATTNc + d] = make_float2(a0, a1);
        }
        if (nhi < Nn) {
            float a2 = o_acc[on][2] * inv1, a3 = o_acc[on][3] * inv1;
            a2 = a2 * fminf(fmaxf(a2 + 3.f, 0.f), 6.f) * (1.f / 6.f);
            a3 = a3 * fminf(fmaxf(a3 + 3.f, 0.f), 6.f) * (1.f / 6.f);
            *(float2*)&g_o[((size_t)b * Nn + nhi) * VAL_ATTNc + d] = make_float2(a2, a3);
        }
    }
}

// ---------------- launch ----------------
extern "C" void kernel_launch(void* const* d_in, const int* in_sizes, int n_in,
                              void* d_out, int out_size) {
    (void)in_sizes; (void)n_in; (void)out_size;
    const float* x      = (const float*)d_in[0];
    const float* qkv_w  = (const float*)d_in[1];
    const float* qkv_g  = (const float*)d_in[2];
    const float* qkv_b  = (const float*)d_in[3];
    const float* qkv_m  = (const float*)d_in[4];
    const float* qkv_v  = (const float*)d_in[5];
    const float* ab     = (const float*)d_in[6];
    const float* proj_w = (const float*)d_in[7];
    const float* proj_g = (const float*)d_in[8];
    const float* proj_b = (const float*)d_in[9];
    const float* proj_m = (const float*)d_in[10];
    const float* proj_v = (const float*)d_in[11];
    const int*   idxs   = (const int*)d_in[12];
    float* out = (float*)d_out;

    bn_coef_kernel<<<6, 256>>>(qkv_g, qkv_b, qkv_m, qkv_v, proj_g, proj_b, proj_m, proj_v);
    bias_kernel<<<(Nn * Nn + 255) / 256, 256>>>(ab, idxs);

    cvt_hilo_kernel<<<(Bc * Nn * DIMc / 4 + 255) / 256, 256>>>(x, 0, Bc * Nn * DIMc / 4);
    cvt_hilo_kernel<<<(QKV_OUTc * DIMc / 4 + 255) / 256, 256>>>(qkv_w, 1, QKV_OUTc * DIMc / 4);
    cvt_hilo_kernel<<<(DIMc * VAL_ATTNc / 4 + 255) / 256, 256>>>(proj_w, 3, DIMc * VAL_ATTNc / 4);

    mma_gemm_kernel<<<dim3(196, 12), 256>>>(0, nullptr);   // QKV

    vtrans_kernel<<<dim3(Bc * Hh, 13, 2), 256>>>();        // V -> V^T split-bf16

    cudaFuncSetAttribute(attn_mma_kernel, cudaFuncAttributeMaxDynamicSharedMemorySize, ATTN_SMEM_B);
    attn_mma_kernel<<<dim3(7, Hh, Bc), 256, ATTN_SMEM_B>>>();

    cvt_hilo_kernel<<<(Bc * Nn * VAL_ATTNc / 4 + 255) / 256, 256>>>(nullptr, 2, Bc * Nn * VAL_ATTNc / 4);
    mma_gemm_kernel<<<dim3(196, 4), 256>>>(1, out);        // proj
}

// round 12
// speedup vs baseline: 2.5937x; 1.0822x over previous
#include <cuda_runtime.h>
#include <cuda_bf16.h>
#include <math.h>
#include <cstdint>

#define Bc 32
#define Nn 784
#define DIMc 512
#define Hh 8
#define KDc 32
#define VDc 128
#define QKV_OUTc 1536
#define VAL_ATTNc 1024
#define SCALE 0.17677669529663687f
#define LOG2E 1.4426950408889634f

// ---------------- scratch (static device globals) ----------------
__device__ float g_v[Bc * Hh * Nn * VDc];          // [bh][n][128] fp32
__device__ float g_bias[Hh * Nn * Nn];             // [h][n][m]
__device__ float g_qs[QKV_OUTc], g_qbb[QKV_OUTc];
__device__ float g_ps[DIMc], g_pbb[DIMc];

// split-bf16 buffers
__device__ __nv_bfloat16 g_qh[Bc * Hh * Nn * KDc], g_ql[Bc * Hh * Nn * KDc];   // [bh][n][32]
__device__ __nv_bfloat16 g_kh[Bc * Hh * Nn * KDc], g_kl[Bc * Hh * Nn * KDc];
__device__ __nv_bfloat16 g_vth[Bc * Hh * VDc * Nn], g_vtl[Bc * Hh * VDc * Nn]; // [bh][d][n]
__device__ __nv_bfloat16 g_xh[Bc * Nn * DIMc],  g_xl[Bc * Nn * DIMc];
__device__ __nv_bfloat16 g_wqh[QKV_OUTc * DIMc], g_wql[QKV_OUTc * DIMc];
__device__ __nv_bfloat16 g_oh[Bc * Nn * VAL_ATTNc], g_ol[Bc * Nn * VAL_ATTNc];
__device__ __nv_bfloat16 g_wph[DIMc * VAL_ATTNc], g_wpl[DIMc * VAL_ATTNc];

// ---------------- helpers ----------------
static __device__ __forceinline__ unsigned pk_bf(__nv_bfloat16 a, __nv_bfloat16 b) {
    return ((unsigned)__bfloat16_as_ushort(b) << 16) | (unsigned)__bfloat16_as_ushort(a);
}
static __device__ __forceinline__ unsigned pk_f2(float a, float b) {
    return pk_bf(__float2bfloat16(a), __float2bfloat16(b));
}
static __device__ __forceinline__ void mma_bf16(float* d, const unsigned* a, const unsigned* b) {
    asm("mma.sync.aligned.m16n8k16.row.col.f32.bf16.bf16.f32 "
        "{%0,%1,%2,%3}, {%4,%5,%6,%7}, {%8,%9}, {%0,%1,%2,%3};"
        : "+f"(d[0]), "+f"(d[1]), "+f"(d[2]), "+f"(d[3])
        : "r"(a[0]), "r"(a[1]), "r"(a[2]), "r"(a[3]), "r"(b[0]), "r"(b[1]));
}
static __device__ __forceinline__ uint32_t sm_u32(const void* p) {
    return (uint32_t)__cvta_generic_to_shared(p);
}
static __device__ __forceinline__ void ldsm4(unsigned* r, uint32_t a) {
    asm volatile("ldmatrix.sync.aligned.m8n8.x4.shared.b16 {%0,%1,%2,%3}, [%4];"
        : "=r"(r[0]), "=r"(r[1]), "=r"(r[2]), "=r"(r[3]) : "r"(a));
}
// cp.async 8B with zero-fill when sz==0 (keeps OOB masking semantics)
static __device__ __forceinline__ void cpa8(uint32_t d, const void* s, int sz) {
    asm volatile("cp.async.ca.shared.global [%0], [%1], 8, %2;"
        :: "r"(d), "l"(__cvta_generic_to_global(s)), "r"(sz) : "memory");
}
#define CP_COMMIT() asm volatile("cp.async.commit_group;" ::: "memory")
#define CP_WAIT0()  asm volatile("cp.async.wait_group 0;" ::: "memory")

// fast 2^t on fma/alu pipes (MUFU rt=8 is the softmax bottleneck otherwise)
static __device__ __forceinline__ float exp2_fast(float t) {
    t = fminf(fmaxf(t, -120.f), 120.f);
    float r = t + 12582912.f;
    int n = __float_as_int(r) - 0x4B400000;
    float f = t - (r - 12582912.f);
    float g = f * 0.6931471805599453f;
    float p = fmaf(g, 0.0083333333f, 0.0416666667f);
    p = fmaf(p, g, 0.1666666667f);
    p = fmaf(p, g, 0.5f);
    p = fmaf(p, g, 1.0f);
    p = fmaf(p, g, 1.0f);
    return __int_as_float(__float_as_int(p) + (n << 23));
}

// ---------------- BN coefficient folding ----------------
__global__ void bn_coef_kernel(const float* __restrict__ qg, const float* __restrict__ qb,
                               const float* __restrict__ qm, const float* __restrict__ qv,
                               const float* __restrict__ pg, const float* __restrict__ pb,
                               const float* __restrict__ pm, const float* __restrict__ pv) {
    int i = blockIdx.x * 256 + threadIdx.x;
    if (i < QKV_OUTc) {
        float s = qg[i] * rsqrtf(qv[i] + 1e-5f);
        g_qs[i] = s;
        g_qbb[i] = qb[i] - qm[i] * s;
    }
    if (i < DIMc) {
        float s = pg[i] * rsqrtf(pv[i] + 1e-5f);
        g_ps[i] = s;
        g_pbb[i] = pb[i] - pm[i] * s;
    }
}

// ---------------- bias gather ----------------
__global__ void bias_kernel(const float* __restrict__ ab, const int* __restrict__ idxs) {
    int nm = blockIdx.x * 256 + threadIdx.x;
    if (nm < Nn * Nn) {
        int idx = idxs[nm];
#pragma unroll
        for (int h = 0; h < Hh; h++)
            g_bias[h * Nn * Nn + nm] = ab[h * Nn + idx];
    }
}

// ---------------- fp32 -> hi/lo bf16 conversion (x, qkv_w, proj_w) ----------------
__global__ void cvt_hilo_kernel(const float* __restrict__ s, int which, int n4) {
    int i = blockIdx.x * 256 + threadIdx.x;
    if (i >= n4) return;
    const float4* sp = (const float4*)s;
    __nv_bfloat16 *h, *l;
    if (which == 0)      { h = g_xh;  l = g_xl;  }
    else if (which == 1) { h = g_wqh; l = g_wql; }
    else                 { h = g_wph; l = g_wpl; }
    float4 v = sp[i];
    __nv_bfloat16 h0 = __float2bfloat16(v.x), h1 = __float2bfloat16(v.y);
    __nv_bfloat16 h2 = __float2bfloat16(v.z), h3 = __float2bfloat16(v.w);
    __nv_bfloat16 l0 = __float2bfloat16(v.x - __bfloat162float(h0));
    __nv_bfloat16 l1 = __float2bfloat16(v.y - __bfloat162float(h1));
    __nv_bfloat16 l2 = __float2bfloat16(v.z - __bfloat162float(h2));
    __nv_bfloat16 l3 = __float2bfloat16(v.w - __bfloat162float(h3));
    ((uint2*)h)[i] = make_uint2(pk_bf(h0, h1), pk_bf(h2, h3));
    ((uint2*)l)[i] = make_uint2(pk_bf(l0, l1), pk_bf(l2, l3));
}

// ---------------- V transpose + split: g_v[bh][n][d] -> g_vt{h,l}[bh][d][n] ----------------
__global__ __launch_bounds__(256) void vtrans_kernel() {
    __shared__ float Ts[64][65];
    int bh = blockIdx.x, n0 = blockIdx.y * 64, d0 = blockIdx.z * 64;
    int t = threadIdx.x;
#pragma unroll
    for (int e = t; e < 4096; e += 256) {
        int r = e >> 6, c = e & 63;
        Ts[r][c] = (n0 + r < Nn) ? g_v[((size_t)(bh * Nn) + n0 + r) * VDc + d0 + c] : 0.f;
    }
    __syncthreads();
#pragma unroll
    for (int e = t; e < 2048; e += 256) {
        int d = e >> 5, kp = e & 31;
        int n = n0 + 2 * kp;
        if (n < Nn) {
            float v0 = Ts[2 * kp][d], v1 = Ts[2 * kp + 1][d];
            __nv_bfloat16 h0 = __float2bfloat16(v0), h1 = __float2bfloat16(v1);
            size_t idx = ((size_t)(bh * VDc) + d0 + d) * Nn + n;
            *(unsigned*)&g_vth[idx] = pk_bf(h0, h1);
            *(unsigned*)&g_vtl[idx] = pk_bf(__float2bfloat16(v0 - __bfloat162float(h0)),
                                            __float2bfloat16(v1 - __bfloat162float(h1)));
        }
    }
}

// ---------------- qkv scatter: q,k -> packed split-bf16; v -> fp32 ----------------
static __device__ __forceinline__ void qkv_scatter2(int b, int n, int o, float y0, float y1) {
    int h = o / 192, r = o - h * 192;
    int bh = b * Hh + h;
    if (r < 2 * KDc) {
        __nv_bfloat16 h0 = __float2bfloat16(y0), h1 = __float2bfloat16(y1);
        unsigned hi = pk_bf(h0, h1);
        unsigned lo = pk_bf(__float2bfloat16(y0 - __bfloat162float(h0)),
                            __float2bfloat16(y1 - __bfloat162float(h1)));
        if (r < KDc) {
            size_t idx = ((size_t)(bh * Nn) + n) * KDc + r;
            *(unsigned*)&g_qh[idx] = hi; *(unsigned*)&g_ql[idx] = lo;
        } else {
            size_t idx = ((size_t)(bh * Nn) + n) * KDc + (r - KDc);
            *(unsigned*)&g_kh[idx] = hi; *(unsigned*)&g_kl[idx] = lo;
        }
    } else {
        size_t idx = ((size_t)(bh * Nn) + n) * VDc + (r - 2 * KDc);
        g_v[idx] = y0; g_v[idx + 1] = y1;
    }
}

// ---------------- split-bf16 mma.sync GEMM, 2-stage cp.async pipeline ----------------
// smem stage layout (per 40960B stage): Ah@0 Al@10240 Bh@20480 Bl@30720; SSTR=40.
#define SSTR 40
#define GSTG 40960
__global__ __launch_bounds__(256, 2) void mma_gemm_kernel(int mode, float* __restrict__ out) {
    extern __shared__ __align__(16) char dsm[];
    int t = threadIdx.x;
    int lane = t & 31, wid = t >> 5;
    int g = lane >> 2, tg = lane & 3;
    int sub = lane >> 3, rr = lane & 7;
    int warp_m = wid >> 2, warp_n = wid & 3;
    int m0 = blockIdx.x * 128, o0 = blockIdx.y * 128;

    const __nv_bfloat16 *Ah, *Al, *Bh, *Bl;
    int K;
    if (mode == 0) { Ah = g_xh; Al = g_xl; Bh = g_wqh; Bl = g_wql; K = DIMc; }
    else           { Ah = g_oh; Al = g_ol; Bh = g_wph; Bl = g_wpl; K = VAL_ATTNc; }

    uint32_t sb = sm_u32(dsm);
    uint32_t a_off = (uint32_t)(((warp_m * 64 + (sub & 1) * 8 + rr) * SSTR + (sub >> 1) * 8) * 2);
    uint32_t b_off = (sub < 2 ? 20480u : 30720u) +
                     (uint32_t)(((warp_n * 32 + rr) * SSTR + (sub & 1) * 8) * 2);

    float acc[4][4][4];
#pragma unroll
    for (int i = 0; i < 4; i++)
#pragma unroll
        for (int j = 0; j < 4; j++)
#pragma unroll
            for (int c = 0; c < 4; c++) acc[i][j][c] = 0.f;

    int T = K >> 5;
    // --- loader: tile it -> stage stg (8B chunks; SSTR rows are 8B-aligned) ---
#define G_LOAD(IT, STG) do {                                                      \
        int _k0 = (IT) << 5;                                                      \
        uint32_t _base = sb + (STG) * GSTG;                                       \
        _Pragma("unroll")                                                         \
        for (int ii = 0; ii < 4; ii++) {                                          \
            int e = t + 256 * ii;                                                 \
            int r = e >> 3, c = e & 7;                                            \
            uint32_t so = _base + (uint32_t)(r * 80 + 8 * c);                     \
            size_t gi = (size_t)(m0 + r) * K + _k0 + 4 * c;                       \
            size_t gj = (size_t)(o0 + r) * K + _k0 + 4 * c;                       \
            cpa8(so,         Ah + gi, 8);                                         \
            cpa8(so + 10240, Al + gi, 8);                                         \
            cpa8(so + 20480, Bh + gj, 8);                                         \
            cpa8(so + 30720, Bl + gj, 8);                                         \
        }                                                                         \
        CP_COMMIT();                                                              \
    } while (0)

    G_LOAD(0, 0);
    for (int it = 0; it < T; it++) {
        CP_WAIT0();
        __syncthreads();
        if (it + 1 < T) G_LOAD(it + 1, (it + 1) & 1);
        uint32_t base = sb + (it & 1) * GSTG;
#pragma unroll
        for (int kk = 0; kk < 2; kk++) {
            unsigned ah[4][4], al[4][4], bb[4][4];
#pragma unroll
            for (int mi = 0; mi < 4; mi++) {
                uint32_t off = (uint32_t)((mi * 16 * SSTR + kk * 16) * 2);
                ldsm4(ah[mi], base + a_off + off);
                ldsm4(al[mi], base + 10240 + a_off + off);
            }
#pragma unroll
            for (int nj = 0; nj < 4; nj++)
                ldsm4(bb[nj], base + b_off + (uint32_t)((nj * 8 * SSTR + kk * 16) * 2));
#pragma unroll
            for (int mi = 0; mi < 4; mi++)
#pragma unroll
                for (int nj = 0; nj < 4; nj++) {
                    mma_bf16(acc[mi][nj], ah[mi], bb[nj]);      // hi*hi
                    mma_bf16(acc[mi][nj], ah[mi], bb[nj] + 2);  // hi*lo
                    mma_bf16(acc[mi][nj], al[mi], bb[nj]);      // lo*hi
                }
        }
    }
#undef G_LOAD

#pragma unroll
    for (int mi = 0; mi < 4; mi++) {
        int m_lo = m0 + warp_m * 64 + mi * 16 + g;
        int m_hi = m_lo + 8;
        if (mode == 0) {
            int b0 = m_lo / Nn, n0q = m_lo - b0 * Nn;
            int b1 = m_hi / Nn, n1q = m_hi - b1 * Nn;
#pragma unroll
            for (int nj = 0; nj < 4; nj++) {
                int o = o0 + warp_n * 32 + nj * 8 + 2 * tg;
                qkv_scatter2(b0, n0q, o, acc[mi][nj][0] * g_qs[o] + g_qbb[o],
                                         acc[mi][nj][1] * g_qs[o + 1] + g_qbb[o + 1]);
                qkv_scatter2(b1, n1q, o, acc[mi][nj][2] * g_qs[o] + g_qbb[o],
                                         acc[mi][nj][3] * g_qs[o + 1] + g_qbb[o + 1]);
            }
        } else {
#pragma unroll
            for (int nj = 0; nj < 4; nj++) {
                int o = o0 + warp_n * 32 + nj * 8 + 2 * tg;
                float s0 = g_ps[o], s1 = g_ps[o + 1];
                float c0 = g_pbb[o], c1 = g_pbb[o + 1];
                *(float2*)&out[(size_t)m_lo * DIMc + o] =
                    make_float2(acc[mi][nj][0] * s0 + c0, acc[mi][nj][1] * s1 + c1);
                *(float2*)&out[(size_t)m_hi * DIMc + o] =
                    make_float2(acc[mi][nj][2] * s0 + c0, acc[mi][nj][3] * s1 + c1);
            }
        }
    }
}

// ---------------- tensor-core attention, 2-stage cp.async pipeline ----------------
// dyn smem: Qh@0 Ql@10240 | stage s @ 20480+s*47104: Kh@0 Kl@5120 Vh@10240 Vl@28672
#define ASTG 47104
#define ATTN_SMEM_B 114688
#define VSTR 72

__global__ __launch_bounds__(256) void attn_mma_kernel() {
    extern __shared__ __align__(16) char dsm[];
    __nv_bfloat16* Qh_s = (__nv_bfloat16*)(dsm);
    __nv_bfloat16* Ql_s = (__nv_bfloat16*)(dsm + 10240);

    int n0q = blockIdx.x * 128;
    int h = blockIdx.y, b = blockIdx.z;
    int bh = b * Hh + h;
    int t = threadIdx.x, w = t >> 5, lane = t & 31;
    int g = lane >> 2, tg = lane & 3;
    int sub = lane >> 3, rr = lane & 7;

    const __nv_bfloat16* qhB = g_qh + (size_t)(bh * Nn) * KDc;
    const __nv_bfloat16* qlB = g_ql + (size_t)(bh * Nn) * KDc;
    const __nv_bfloat16* khB = g_kh + (size_t)(bh * Nn) * KDc;
    const __nv_bfloat16* klB = g_kl + (size_t)(bh * Nn) * KDc;
    const __nv_bfloat16* vhB = g_vth + (size_t)(bh * VDc) * Nn;
    const __nv_bfloat16* vlB = g_vtl + (size_t)(bh * VDc) * Nn;
    const float* biasb = g_bias + (size_t)h * Nn * Nn;

    uint32_t sb = sm_u32(dsm);
    uint32_t q_moff = (uint32_t)(((16 * w + (sub & 1) * 8 + rr) * SSTR + (sub >> 1) * 8) * 2);
    uint32_t k_rel = (sub < 2 ? 0u : 5120u) + (uint32_t)((rr * SSTR + (sub & 1) * 8) * 2);
    uint32_t v_rel = 10240u + (sub < 2 ? 0u : 18432u) + (uint32_t)((rr * VSTR + (sub & 1) * 8) * 2);

    // load Q tile (128 x 32), rows clamped at boundary
#pragma unroll
    for (int e = t; e < 512; e += 256) {
        int r = e >> 2, c = e & 3;
        int n = n0q + r; if (n >= Nn) n = Nn - 1;
        *(uint4*)&Qh_s[r * SSTR + 8 * c] = *(const uint4*)&qhB[(size_t)n * KDc + 8 * c];
        *(uint4*)&Ql_s[r * SSTR + 8 * c] = *(const uint4*)&qlB[(size_t)n * KDc + 8 * c];
    }

    // --- KV tile loader: tile it -> stage stg ---
#define KV_LOAD(IT, STG) do {                                                     \
        int _m0 = (IT) * 64;                                                      \
        uint32_t _base = sb + 20480u + (STG) * ASTG;                              \
        _Pragma("unroll")                                                         \
        for (int ii = 0; ii < 2; ii++) {                                          \
            int e = t + 256 * ii;                                                 \
            int r = e >> 3, c = e & 7;                                            \
            int m = _m0 + r;                                                      \
            int sz = (m < Nn) ? 8 : 0;                                            \
            int mc = (m < Nn) ? m : 0;                                            \
            uint32_t so = _base + (uint32_t)(r * 80 + 8 * c);                     \
            cpa8(so,        khB + (size_t)mc * KDc + 4 * c, sz);                  \
            cpa8(so + 5120, klB + (size_t)mc * KDc + 4 * c, sz);                  \
        }                                                                         \
        _Pragma("unroll")                                                         \
        for (int ii = 0; ii < 8; ii++) {                                          \
            int e = t + 256 * ii;                                                 \
            int r = e >> 4, c = e & 15;                                           \
            int m = _m0 + 4 * c;                                                  \
            int sz = (m < Nn) ? 8 : 0;                                            \
            int mc = (m < Nn) ? m : 0;                                            \
            uint32_t so = _base + 10240u + (uint32_t)(r * 144 + 8 * c);           \
            cpa8(so,         vhB + (size_t)r * Nn + mc, sz);                      \
            cpa8(so + 18432, vlB + (size_t)r * Nn + mc, sz);                      \
        }                                                                         \
        CP_COMMIT();                                                              \
    } while (0)

    float o_acc[16][4];
#pragma unroll
    for (int on = 0; on < 16; on++)
#pragma unroll
        for (int c = 0; c < 4; c++) o_acc[on][c] = 0.f;
    float rs0 = 0.f, rs1 = 0.f;

    int row0 = n0q + 16 * w + g;
    int nc0 = (row0 < Nn) ? row0 : (Nn - 1);
    int nc1 = (row0 + 8 < Nn) ? (row0 + 8) : (Nn - 1);

    const int T = (Nn + 63) / 64;   // 13
    KV_LOAD(0, 0);
    for (int it = 0; it < T; it++) {
        CP_WAIT0();
        __syncthreads();
        if (it + 1 < T) KV_LOAD(it + 1, (it + 1) & 1);
        int m0 = it * 64;
        uint32_t stb = sb + 20480u + (it & 1) * ASTG;
        uint32_t k_base = stb + k_rel;
        uint32_t v_base = stb + v_rel;

        // ---- S = Q K^T ----
        float sa[8][4];
#pragma unroll
        for (int nt = 0; nt < 8; nt++)
#pragma unroll
            for (int c = 0; c < 4; c++) sa[nt][c] = 0.f;
#pragma unroll
        for (int kt = 0; kt < 2; kt++) {
            unsigned ah[4], al[4];
            ldsm4(ah, sb + q_moff + kt * 32);
            ldsm4(al, sb + 10240u + q_moff + kt * 32);
#pragma unroll
            for (int nt = 0; nt < 8; nt++) {
                unsigned bb[4];
                ldsm4(bb, k_base + (uint32_t)((nt * 8 * SSTR) * 2 + kt * 32));
                mma_bf16(sa[nt], ah, bb);
                mma_bf16(sa[nt], ah, bb + 2);
                mma_bf16(sa[nt], al, bb);
            }
        }

        // ---- bias + exp (poly) -> P frags in registers ----
        unsigned ph[4][4], pl[4][4];
#pragma unroll
        for (int nt = 0; nt < 8; nt++) {
            int mcol = m0 + 8 * nt + 2 * tg;
            float2 bb0, bb1;
            if (mcol < Nn) {
                bb0 = *(const float2*)&biasb[(size_t)nc0 * Nn + mcol];
                bb1 = *(const float2*)&biasb[(size_t)nc1 * Nn + mcol];
            } else {
                bb0 = make_float2(-21000.f, -21000.f);
                bb1 = bb0;
            }
            float p0 = exp2_fast(fmaf(sa[nt][0], SCALE * LOG2E, bb0.x * LOG2E));
            float p1 = exp2_fast(fmaf(sa[nt][1], SCALE * LOG2E, bb0.y * LOG2E));
            float p2 = exp2_fast(fmaf(sa[nt][2], SCALE * LOG2E, bb1.x * LOG2E));
            float p3 = exp2_fast(fmaf(sa[nt][3], SCALE * LOG2E, bb1.y * LOG2E));
            rs0 += p0 + p1;
            rs1 += p2 + p3;
            __nv_bfloat16 h0 = __float2bfloat16(p0), h1 = __float2bfloat16(p1);
            __nv_bfloat16 h2 = __float2bfloat16(p2), h3 = __float2bfloat16(p3);
            unsigned uh0 = pk_bf(h0, h1), uh1 = pk_bf(h2, h3);
            unsigned ul0 = pk_f2(p0 - __bfloat162float(h0), p1 - __bfloat162float(h1));
            unsigned ul1 = pk_f2(p2 - __bfloat162float(h2), p3 - __bfloat162float(h3));
            int kv = nt >> 1;
            if ((nt & 1) == 0) {
                ph[kv][0] = uh0; ph[kv][1] = uh1;
                pl[kv][0] = ul0; pl[kv][1] = ul1;
            } else {
                ph[kv][2] = uh0; ph[kv][3] = uh1;
                pl[kv][2] = ul0; pl[kv][3] = ul1;
            }
        }

        // ---- O += P V ----
#pragma unroll
        for (int kv = 0; kv < 4; kv++) {
#pragma unroll
            for (int on = 0; on < 16; on++) {
                unsigned bb[4];
                ldsm4(bb, v_base + (uint32_t)((on * 8 * VSTR) * 2 + kv * 32));
                mma_bf16(o_acc[on], ph[kv], bb);
                mma_bf16(o_acc[on], ph[kv], bb + 2);
                mma_bf16(o_acc[on], pl[kv], bb);
            }
        }
    }
#undef KV_LOAD

    // reduce row sums across the 4 tg lanes of each group
    rs0 += __shfl_xor_sync(0xffffffffu, rs0, 1);
    rs0 += __shfl_xor_sync(0xffffffffu, rs0, 2);
    rs1 += __shfl_xor_sync(0xffffffffu, rs1, 1);
    rs1 += __shfl_xor_sync(0xffffffffu, rs1, 2);
    float inv0 = 1.f / rs0, inv1 = 1.f / rs1;

    // normalize + hardswish + store split-bf16 directly (no fp32 g_o pass)
    int nlo = n0q + 16 * w + g, nhi = nlo + 8;
#pragma unroll
    for (int on = 0; on < 16; on++) {
        int d = h * VDc + 8 * on + 2 * tg;
        if (nlo < Nn) {
            float a0 = o_acc[on][0] * inv0, a1 = o_acc[on][1] * inv0;
            a0 = a0 * fminf(fmaxf(a0 + 3.f, 0.f), 6.f) * (1.f / 6.f);
            a1 = a1 * fminf(fmaxf(a1 + 3.f, 0.f), 6.f) * (1.f / 6.f);
            size_t idx = ((size_t)b * Nn + nlo) * VAL_ATTNc + d;
            __nv_bfloat16 h0 = __float2bfloat16(a0), h1 = __float2bfloat16(a1);
            *(unsigned*)&g_oh[idx] = pk_bf(h0, h1);
            *(unsigned*)&g_ol[idx] = pk_f2(a0 - __bfloat162float(h0), a1 - __bfloat162float(h1));
        }
        if (nhi < Nn) {
            float a2 = o_acc[on][2] * inv1, a3 = o_acc[on][3] * inv1;
            a2 = a2 * fminf(fmaxf(a2 + 3.f, 0.f), 6.f) * (1.f / 6.f);
            a3 = a3 * fminf(fmaxf(a3 + 3.f, 0.f), 6.f) * (1.f / 6.f);
            size_t idx = ((size_t)b * Nn + nhi) * VAL_ATTNc + d;
            __nv_bfloat16 h2 = __float2bfloat16(a2), h3 = __float2bfloat16(a3);
            *(unsigned*)&g_oh[idx] = pk_bf(h2, h3);
            *(unsigned*)&g_ol[idx] = pk_f2(a2 - __bfloat162float(h2), a3 - __bfloat162float(h3));
        }
    }
}

// ---------------- launch ----------------
extern "C" void kernel_launch(void* const* d_in, const int* in_sizes, int n_in,
                              void* d_out, int out_size) {
    (void)in_sizes; (void)n_in; (void)out_size;
    const float* x      = (const float*)d_in[0];
    const float* qkv_w  = (const float*)d_in[1];
    const float* qkv_g  = (const float*)d_in[2];
    const float* qkv_b  = (const float*)d_in[3];
    const float* qkv_m  = (const float*)d_in[4];
    const float* qkv_v  = (const float*)d_in[5];
    const float* ab     = (const float*)d_in[6];
    const float* proj_w = (const float*)d_in[7];
    const float* proj_g = (const float*)d_in[8];
    const float* proj_b = (const float*)d_in[9];
    const float* proj_m = (const float*)d_in[10];
    const float* proj_v = (const float*)d_in[11];
    const int*   idxs   = (const int*)d_in[12];
    float* out = (float*)d_out;

    bn_coef_kernel<<<6, 256>>>(qkv_g, qkv_b, qkv_m, qkv_v, proj_g, proj_b, proj_m, proj_v);
    bias_kernel<<<(Nn * Nn + 255) / 256, 256>>>(ab, idxs);

    cvt_hilo_kernel<<<(Bc * Nn * DIMc / 4 + 255) / 256, 256>>>(x, 0, Bc * Nn * DIMc / 4);
    cvt_hilo_kernel<<<(QKV_OUTc * DIMc / 4 + 255) / 256, 256>>>(qkv_w, 1, QKV_OUTc * DIMc / 4);
    cvt_hilo_kernel<<<(DIMc * VAL_ATTNc / 4 + 255) / 256, 256>>>(proj_w, 3, DIMc * VAL_ATTNc / 4);

    cudaFuncSetAttribute(mma_gemm_kernel, cudaFuncAttributeMaxDynamicSharedMemorySize, 2 * GSTG);
    mma_gemm_kernel<<<dim3(196, 12), 256, 2 * GSTG>>>(0, nullptr);   // QKV

    vtrans_kernel<<<dim3(Bc * Hh, 13, 2), 256>>>();                  // V -> V^T split-bf16

    cudaFuncSetAttribute(attn_mma_kernel, cudaFuncAttributeMaxDynamicSharedMemorySize, ATTN_SMEM_B);
    attn_mma_kernel<<<dim3(7, Hh, Bc), 256, ATTN_SMEM_B>>>();

    mma_gemm_kernel<<<dim3(196, 4), 256, 2 * GSTG>>>(1, out);        // proj
}

// round 13
// speedup vs baseline: 2.7407x; 1.0567x over previous
#include <cuda_runtime.h>
#include <cuda_bf16.h>
#include <math.h>
#include <cstdint>

#define Bc 32
#define Nn 784
#define DIMc 512
#define Hh 8
#define KDc 32
#define VDc 128
#define QKV_OUTc 1536
#define VAL_ATTNc 1024
#define SCALE 0.17677669529663687f
#define LOG2E 1.4426950408889634f

// ---------------- scratch (static device globals) ----------------
__device__ float g_bias[Hh * Nn * Nn];             // [h][n][m]
__device__ float g_qs[QKV_OUTc], g_qbb[QKV_OUTc];
__device__ float g_ps[DIMc], g_pbb[DIMc];

// split-bf16 buffers
__device__ __nv_bfloat16 g_qh[Bc * Hh * Nn * KDc], g_ql[Bc * Hh * Nn * KDc];   // [bh][n][32]
__device__ __nv_bfloat16 g_kh[Bc * Hh * Nn * KDc], g_kl[Bc * Hh * Nn * KDc];
__device__ __nv_bfloat16 g_vh[Bc * Hh * Nn * VDc], g_vl[Bc * Hh * Nn * VDc];   // [bh][n][128] row-major
__device__ __nv_bfloat16 g_xh[Bc * Nn * DIMc],  g_xl[Bc * Nn * DIMc];
__device__ __nv_bfloat16 g_wqh[QKV_OUTc * DIMc], g_wql[QKV_OUTc * DIMc];
__device__ __nv_bfloat16 g_oh[Bc * Nn * VAL_ATTNc], g_ol[Bc * Nn * VAL_ATTNc];
__device__ __nv_bfloat16 g_wph[DIMc * VAL_ATTNc], g_wpl[DIMc * VAL_ATTNc];

// ---------------- helpers ----------------
static __device__ __forceinline__ unsigned pk_bf(__nv_bfloat16 a, __nv_bfloat16 b) {
    return ((unsigned)__bfloat16_as_ushort(b) << 16) | (unsigned)__bfloat16_as_ushort(a);
}
static __device__ __forceinline__ unsigned pk_f2(float a, float b) {
    return pk_bf(__float2bfloat16(a), __float2bfloat16(b));
}
static __device__ __forceinline__ void mma_bf16(float* d, const unsigned* a, const unsigned* b) {
    asm("mma.sync.aligned.m16n8k16.row.col.f32.bf16.bf16.f32 "
        "{%0,%1,%2,%3}, {%4,%5,%6,%7}, {%8,%9}, {%0,%1,%2,%3};"
        : "+f"(d[0]), "+f"(d[1]), "+f"(d[2]), "+f"(d[3])
        : "r"(a[0]), "r"(a[1]), "r"(a[2]), "r"(a[3]), "r"(b[0]), "r"(b[1]));
}
static __device__ __forceinline__ uint32_t sm_u32(const void* p) {
    return (uint32_t)__cvta_generic_to_shared(p);
}
static __device__ __forceinline__ void ldsm4(unsigned* r, uint32_t a) {
    asm volatile("ldmatrix.sync.aligned.m8n8.x4.shared.b16 {%0,%1,%2,%3}, [%4];"
        : "=r"(r[0]), "=r"(r[1]), "=r"(r[2]), "=r"(r[3]) : "r"(a));
}
static __device__ __forceinline__ void ldsm4t(unsigned* r, uint32_t a) {
    asm volatile("ldmatrix.sync.aligned.m8n8.x4.trans.shared.b16 {%0,%1,%2,%3}, [%4];"
        : "=r"(r[0]), "=r"(r[1]), "=r"(r[2]), "=r"(r[3]) : "r"(a));
}
// cp.async 8B with zero-fill when sz==0 (keeps OOB masking semantics)
static __device__ __forceinline__ void cpa8(uint32_t d, const void* s, int sz) {
    asm volatile("cp.async.ca.shared.global [%0], [%1], 8, %2;"
        :: "r"(d), "l"(__cvta_generic_to_global(s)), "r"(sz) : "memory");
}
#define CP_COMMIT() asm volatile("cp.async.commit_group;" ::: "memory")
#define CP_WAIT0()  asm volatile("cp.async.wait_group 0;" ::: "memory")

// fast 2^t on fma/alu pipes (MUFU rt=8 is the softmax bottleneck otherwise)
static __device__ __forceinline__ float exp2_fast(float t) {
    t = fmaxf(t, -120.f);                         // lower clamp only (mask sentinel)
    float r = t + 12582912.f;
    int n = __float_as_int(r) - 0x4B400000;
    float f = t - (r - 12582912.f);
    float g = f * 0.6931471805599453f;
    float p = fmaf(g, 0.0083333333f, 0.0416666667f);
    p = fmaf(p, g, 0.1666666667f);
    p = fmaf(p, g, 0.5f);
    p = fmaf(p, g, 1.0f);
    p = fmaf(p, g, 1.0f);
    return __int_as_float(__float_as_int(p) + (n << 23));
}

// ---------------- BN coefficient folding ----------------
__global__ void bn_coef_kernel(const float* __restrict__ qg, const float* __restrict__ qb,
                               const float* __restrict__ qm, const float* __restrict__ qv,
                               const float* __restrict__ pg, const float* __restrict__ pb,
                               const float* __restrict__ pm, const float* __restrict__ pv) {
    int i = blockIdx.x * 256 + threadIdx.x;
    if (i < QKV_OUTc) {
        float s = qg[i] * rsqrtf(qv[i] + 1e-5f);
        g_qs[i] = s;
        g_qbb[i] = qb[i] - qm[i] * s;
    }
    if (i < DIMc) {
        float s = pg[i] * rsqrtf(pv[i] + 1e-5f);
        g_ps[i] = s;
        g_pbb[i] = pb[i] - pm[i] * s;
    }
}

// ---------------- bias gather ----------------
__global__ void bias_kernel(const float* __restrict__ ab, const int* __restrict__ idxs) {
    int nm = blockIdx.x * 256 + threadIdx.x;
    if (nm < Nn * Nn) {
        int idx = idxs[nm];
#pragma unroll
        for (int h = 0; h < Hh; h++)
            g_bias[h * Nn * Nn + nm] = ab[h * Nn + idx];
    }
}

// ---------------- fp32 -> hi/lo bf16 conversion (x, qkv_w, proj_w) ----------------
__global__ void cvt_hilo_kernel(const float* __restrict__ s, int which, int n4) {
    int i = blockIdx.x * 256 + threadIdx.x;
    if (i >= n4) return;
    const float4* sp = (const float4*)s;
    __nv_bfloat16 *h, *l;
    if (which == 0)      { h = g_xh;  l = g_xl;  }
    else if (which == 1) { h = g_wqh; l = g_wql; }
    else                 { h = g_wph; l = g_wpl; }
    float4 v = sp[i];
    __nv_bfloat16 h0 = __float2bfloat16(v.x), h1 = __float2bfloat16(v.y);
    __nv_bfloat16 h2 = __float2bfloat16(v.z), h3 = __float2bfloat16(v.w);
    __nv_bfloat16 l0 = __float2bfloat16(v.x - __bfloat162float(h0));
    __nv_bfloat16 l1 = __float2bfloat16(v.y - __bfloat162float(h1));
    __nv_bfloat16 l2 = __float2bfloat16(v.z - __bfloat162float(h2));
    __nv_bfloat16 l3 = __float2bfloat16(v.w - __bfloat162float(h3));
    ((uint2*)h)[i] = make_uint2(pk_bf(h0, h1), pk_bf(h2, h3));
    ((uint2*)l)[i] = make_uint2(pk_bf(l0, l1), pk_bf(l2, l3));
}

// ---------------- qkv scatter: q,k,v all packed split-bf16 ----------------
static __device__ __forceinline__ void qkv_scatter2(int b, int n, int o, float y0, float y1) {
    int h = o / 192, r = o - h * 192;
    int bh = b * Hh + h;
    __nv_bfloat16 h0 = __float2bfloat16(y0), h1 = __float2bfloat16(y1);
    unsigned hi = pk_bf(h0, h1);
    unsigned lo = pk_f2(y0 - __bfloat162float(h0), y1 - __bfloat162float(h1));
    __nv_bfloat16 *ph, *pl;
    size_t idx;
    if (r < KDc)            { ph = g_qh; pl = g_ql; idx = ((size_t)(bh * Nn) + n) * KDc + r; }
    else if (r < 2 * KDc)   { ph = g_kh; pl = g_kl; idx = ((size_t)(bh * Nn) + n) * KDc + (r - KDc); }
    else                    { ph = g_vh; pl = g_vl; idx = ((size_t)(bh * Nn) + n) * VDc + (r - 2 * KDc); }
    *(unsigned*)&ph[idx] = hi;
    *(unsigned*)&pl[idx] = lo;
}

// ---------------- split-bf16 mma.sync GEMM, 2-stage cp.async pipeline ----------------
// smem stage layout (per 40960B stage): Ah@0 Al@10240 Bh@20480 Bl@30720; SSTR=40.
#define SSTR 40
#define GSTG 40960
__global__ __launch_bounds__(256, 2) void mma_gemm_kernel(int mode, float* __restrict__ out) {
    extern __shared__ __align__(16) char dsm[];
    int t = threadIdx.x;
    int lane = t & 31, wid = t >> 5;
    int g = lane >> 2, tg = lane & 3;
    int sub = lane >> 3, rr = lane & 7;
    int warp_m = wid >> 2, warp_n = wid & 3;
    int m0 = blockIdx.x * 128, o0 = blockIdx.y * 128;

    const __nv_bfloat16 *Ah, *Al, *Bh, *Bl;
    int K;
    if (mode == 0) { Ah = g_xh; Al = g_xl; Bh = g_wqh; Bl = g_wql; K = DIMc; }
    else           { Ah = g_oh; Al = g_ol; Bh = g_wph; Bl = g_wpl; K = VAL_ATTNc; }

    uint32_t sb = sm_u32(dsm);
    uint32_t a_off = (uint32_t)(((warp_m * 64 + (sub & 1) * 8 + rr) * SSTR + (sub >> 1) * 8) * 2);
    uint32_t b_off = (sub < 2 ? 20480u : 30720u) +
                     (uint32_t)(((warp_n * 32 + rr) * SSTR + (sub & 1) * 8) * 2);

    float acc[4][4][4];
#pragma unroll
    for (int i = 0; i < 4; i++)
#pragma unroll
        for (int j = 0; j < 4; j++)
#pragma unroll
            for (int c = 0; c < 4; c++) acc[i][j][c] = 0.f;

    int T = K >> 5;
#define G_LOAD(IT, STG) do {                                                      \
        int _k0 = (IT) << 5;                                                      \
        uint32_t _base = sb + (STG) * GSTG;                                       \
        _Pragma("unroll")                                                         \
        for (int ii = 0; ii < 4; ii++) {                                          \
            int e = t + 256 * ii;                                                 \
            int r = e >> 3, c = e & 7;                                            \
            uint32_t so = _base + (uint32_t)(r * 80 + 8 * c);                     \
            size_t gi = (size_t)(m0 + r) * K + _k0 + 4 * c;                       \
            size_t gj = (size_t)(o0 + r) * K + _k0 + 4 * c;                       \
            cpa8(so,         Ah + gi, 8);                                         \
            cpa8(so + 10240, Al + gi, 8);                                         \
            cpa8(so + 20480, Bh + gj, 8);                                         \
            cpa8(so + 30720, Bl + gj, 8);                                         \
        }                                                                         \
        CP_COMMIT();                                                              \
    } while (0)

    G_LOAD(0, 0);
    for (int it = 0; it < T; it++) {
        CP_WAIT0();
        __syncthreads();
        if (it + 1 < T) G_LOAD(it + 1, (it + 1) & 1);
        uint32_t base = sb + (it & 1) * GSTG;
#pragma unroll
        for (int kk = 0; kk < 2; kk++) {
            unsigned ah[4][4], al[4][4], bb[4][4];
#pragma unroll
            for (int mi = 0; mi < 4; mi++) {
                uint32_t off = (uint32_t)((mi * 16 * SSTR + kk * 16) * 2);
                ldsm4(ah[mi], base + a_off + off);
                ldsm4(al[mi], base + 10240 + a_off + off);
            }
#pragma unroll
            for (int nj = 0; nj < 4; nj++)
                ldsm4(bb[nj], base + b_off + (uint32_t)((nj * 8 * SSTR + kk * 16) * 2));
#pragma unroll
            for (int mi = 0; mi < 4; mi++)
#pragma unroll
                for (int nj = 0; nj < 4; nj++) {
                    mma_bf16(acc[mi][nj], ah[mi], bb[nj]);      // hi*hi
                    mma_bf16(acc[mi][nj], ah[mi], bb[nj] + 2);  // hi*lo
                    mma_bf16(acc[mi][nj], al[mi], bb[nj]);      // lo*hi
                }
        }
    }
#undef G_LOAD

#pragma unroll
    for (int mi = 0; mi < 4; mi++) {
        int m_lo = m0 + warp_m * 64 + mi * 16 + g;
        int m_hi = m_lo + 8;
        if (mode == 0) {
            int b0 = m_lo / Nn, n0q = m_lo - b0 * Nn;
            int b1 = m_hi / Nn, n1q = m_hi - b1 * Nn;
#pragma unroll
            for (int nj = 0; nj < 4; nj++) {
                int o = o0 + warp_n * 32 + nj * 8 + 2 * tg;
                qkv_scatter2(b0, n0q, o, acc[mi][nj][0] * g_qs[o] + g_qbb[o],
                                         acc[mi][nj][1] * g_qs[o + 1] + g_qbb[o + 1]);
                qkv_scatter2(b1, n1q, o, acc[mi][nj][2] * g_qs[o] + g_qbb[o],
                                         acc[mi][nj][3] * g_qs[o + 1] + g_qbb[o + 1]);
            }
        } else {
#pragma unroll
            for (int nj = 0; nj < 4; nj++) {
                int o = o0 + warp_n * 32 + nj * 8 + 2 * tg;
                float s0 = g_ps[o], s1 = g_ps[o + 1];
                float c0 = g_pbb[o], c1 = g_pbb[o + 1];
                *(float2*)&out[(size_t)m_lo * DIMc + o] =
                    make_float2(acc[mi][nj][0] * s0 + c0, acc[mi][nj][1] * s1 + c1);
                *(float2*)&out[(size_t)m_hi * DIMc + o] =
                    make_float2(acc[mi][nj][2] * s0 + c0, acc[mi][nj][3] * s1 + c1);
            }
        }
    }
}

// ---------------- tensor-core attention ----------------
// dyn smem: Qh@0 Ql@10240 | stage s @ 20480+s*45056: Kh@0 Kl@5120 Vh@10240 Vl@27648
// V stored ROW-major [key][d] (136 bf16 row stride = 272B); PV B-frags via ldmatrix.trans.
#define ASTG 45056
#define ATTN_SMEM_B 110592
#define VROWB 272

__global__ __launch_bounds__(256) void attn_mma_kernel() {
    extern __shared__ __align__(16) char dsm[];
    __nv_bfloat16* Qh_s = (__nv_bfloat16*)(dsm);
    __nv_bfloat16* Ql_s = (__nv_bfloat16*)(dsm + 10240);

    int n0q = blockIdx.x * 128;
    int h = blockIdx.y, b = blockIdx.z;
    int bh = b * Hh + h;
    int t = threadIdx.x, w = t >> 5, lane = t & 31;
    int g = lane >> 2, tg = lane & 3;
    int sub = lane >> 3, rr = lane & 7;

    const __nv_bfloat16* qhB = g_qh + (size_t)(bh * Nn) * KDc;
    const __nv_bfloat16* qlB = g_ql + (size_t)(bh * Nn) * KDc;
    const __nv_bfloat16* khB = g_kh + (size_t)(bh * Nn) * KDc;
    const __nv_bfloat16* klB = g_kl + (size_t)(bh * Nn) * KDc;
    const __nv_bfloat16* vhB = g_vh + (size_t)(bh * Nn) * VDc;
    const __nv_bfloat16* vlB = g_vl + (size_t)(bh * Nn) * VDc;
    const float* biasb = g_bias + (size_t)h * Nn * Nn;

    uint32_t sb = sm_u32(dsm);
    uint32_t q_moff = (uint32_t)(((16 * w + (sub & 1) * 8 + rr) * SSTR + (sub >> 1) * 8) * 2);
    uint32_t k_rel = (sub < 2 ? 0u : 5120u) + (uint32_t)((rr * SSTR + (sub & 1) * 8) * 2);
    // V trans-ldmatrix lane address: mats (k0,d0),(k8,d0),(k0,d8),(k8,d8)
    uint32_t v_lane = (uint32_t)(((sub & 1) * 8 + rr) * VROWB + (sub >> 1) * 16);

    // load Q tile (128 x 32), rows clamped at boundary
#pragma unroll
    for (int e = t; e < 512; e += 256) {
        int r = e >> 2, c = e & 3;
        int n = n0q + r; if (n >= Nn) n = Nn - 1;
        *(uint4*)&Qh_s[r * SSTR + 8 * c] = *(const uint4*)&qhB[(size_t)n * KDc + 8 * c];
        *(uint4*)&Ql_s[r * SSTR + 8 * c] = *(const uint4*)&qlB[(size_t)n * KDc + 8 * c];
    }
    __syncthreads();

    // hoist Q fragments (iteration-invariant) into registers
    unsigned qah[2][4], qal[2][4];
#pragma unroll
    for (int kt = 0; kt < 2; kt++) {
        ldsm4(qah[kt], sb + q_moff + kt * 32);
        ldsm4(qal[kt], sb + 10240u + q_moff + kt * 32);
    }

#define KV_LOAD(IT, STG) do {                                                     \
        int _m0 = (IT) * 64;                                                      \
        uint32_t _base = sb + 20480u + (STG) * ASTG;                              \
        _Pragma("unroll")                                                         \
        for (int ii = 0; ii < 2; ii++) {                                          \
            int e = t + 256 * ii;                                                 \
            int r = e >> 3, c = e & 7;                                            \
            int m = _m0 + r;                                                      \
            int sz = (m < Nn) ? 8 : 0;                                            \
            int mc = (m < Nn) ? m : 0;                                            \
            uint32_t so = _base + (uint32_t)(r * 80 + 8 * c);                     \
            cpa8(so,        khB + (size_t)mc * KDc + 4 * c, sz);                  \
            cpa8(so + 5120, klB + (size_t)mc * KDc + 4 * c, sz);                  \
        }                                                                         \
        _Pragma("unroll")                                                         \
        for (int ii = 0; ii < 8; ii++) {                                          \
            int e = t + 256 * ii;                                                 \
            int r = e >> 5, c = e & 31;                                           \
            int m = _m0 + r;                                                      \
            int sz = (m < Nn) ? 8 : 0;                                            \
            int mc = (m < Nn) ? m : 0;                                            \
            uint32_t so = _base + 10240u + (uint32_t)(r * VROWB + 8 * c);         \
            cpa8(so,         vhB + (size_t)mc * VDc + 4 * c, sz);                 \
            cpa8(so + 17408, vlB + (size_t)mc * VDc + 4 * c, sz);                 \
        }                                                                         \
        CP_COMMIT();                                                              \
    } while (0)

    float o_acc[16][4];
#pragma unroll
    for (int on = 0; on < 16; on++)
#pragma unroll
        for (int c = 0; c < 4; c++) o_acc[on][c] = 0.f;
    float rs0 = 0.f, rs1 = 0.f;

    int row0 = n0q + 16 * w + g;
    int nc0 = (row0 < Nn) ? row0 : (Nn - 1);
    int nc1 = (row0 + 8 < Nn) ? (row0 + 8) : (Nn - 1);

    const int T = (Nn + 63) / 64;   // 13
    KV_LOAD(0, 0);
    for (int it = 0; it < T; it++) {
        CP_WAIT0();
        __syncthreads();
        if (it + 1 < T) KV_LOAD(it + 1, (it + 1) & 1);
        int m0 = it * 64;
        uint32_t stb = sb + 20480u + (it & 1) * ASTG;
        uint32_t k_base = stb + k_rel;
        uint32_t v_base = stb + 10240u + v_lane;

        // ---- prefetch full iteration's bias (hide L2 latency under QK mma) ----
        float2 bia0[8], bia1[8];
#pragma unroll
        for (int nt = 0; nt < 8; nt++) {
            int mcol = m0 + 8 * nt + 2 * tg;
            if (mcol < Nn) {
                bia0[nt] = *(const float2*)&biasb[(size_t)nc0 * Nn + mcol];
                bia1[nt] = *(const float2*)&biasb[(size_t)nc1 * Nn + mcol];
            } else {
                bia0[nt] = make_float2(-21000.f, -21000.f);
                bia1[nt] = bia0[nt];
            }
        }

        // ---- S = Q K^T ----
        float sa[8][4];
#pragma unroll
        for (int nt = 0; nt < 8; nt++)
#pragma unroll
            for (int c = 0; c < 4; c++) sa[nt][c] = 0.f;
#pragma unroll
        for (int kt = 0; kt < 2; kt++) {
#pragma unroll
            for (int nt = 0; nt < 8; nt++) {
                unsigned bb[4];
                ldsm4(bb, k_base + (uint32_t)((nt * 8 * SSTR) * 2 + kt * 32));
                mma_bf16(sa[nt], qah[kt], bb);
                mma_bf16(sa[nt], qah[kt], bb + 2);
                mma_bf16(sa[nt], qal[kt], bb);
            }
        }

        // ---- bias + exp (poly) -> P frags in registers ----
        unsigned ph[4][4], pl[4][4];
#pragma unroll
        for (int nt = 0; nt < 8; nt++) {
            float p0 = exp2_fast(fmaf(sa[nt][0], SCALE * LOG2E, bia0[nt].x * LOG2E));
            float p1 = exp2_fast(fmaf(sa[nt][1], SCALE * LOG2E, bia0[nt].y * LOG2E));
            float p2 = exp2_fast(fmaf(sa[nt][2], SCALE * LOG2E, bia1[nt].x * LOG2E));
            float p3 = exp2_fast(fmaf(sa[nt][3], SCALE * LOG2E, bia1[nt].y * LOG2E));
            rs0 += p0 + p1;
            rs1 += p2 + p3;
            __nv_bfloat16 h0 = __float2bfloat16(p0), h1 = __float2bfloat16(p1);
            __nv_bfloat16 h2 = __float2bfloat16(p2), h3 = __float2bfloat16(p3);
            unsigned uh0 = pk_bf(h0, h1), uh1 = pk_bf(h2, h3);
            unsigned ul0 = pk_f2(p0 - __bfloat162float(h0), p1 - __bfloat162float(h1));
            unsigned ul1 = pk_f2(p2 - __bfloat162float(h2), p3 - __bfloat162float(h3));
            int kv = nt >> 1;
            if ((nt & 1) == 0) {
                ph[kv][0] = uh0; ph[kv][1] = uh1;
                pl[kv][0] = ul0; pl[kv][1] = ul1;
            } else {
                ph[kv][2] = uh0; ph[kv][3] = uh1;
                pl[kv][2] = ul0; pl[kv][3] = ul1;
            }
        }

        // ---- O += P V : ldmatrix.trans on row-major V; each x4 -> 2 n-blocks ----
#pragma unroll
        for (int kv = 0; kv < 4; kv++) {
            uint32_t kvb = v_base + (uint32_t)(kv * 16 * VROWB);
#pragma unroll
            for (int op = 0; op < 8; op++) {
                unsigned vh[4], vl[4];
                ldsm4t(vh, kvb + (uint32_t)(op * 32));
                ldsm4t(vl, kvb + 17408u + (uint32_t)(op * 32));
                mma_bf16(o_acc[2 * op],     ph[kv], vh);
                mma_bf16(o_acc[2 * op],     ph[kv], vl);
                mma_bf16(o_acc[2 * op],     pl[kv], vh);
                mma_bf16(o_acc[2 * op + 1], ph[kv], vh + 2);
                mma_bf16(o_acc[2 * op + 1], ph[kv], vl + 2);
                mma_bf16(o_acc[2 * op + 1], pl[kv], vh + 2);
            }
        }
    }
#undef KV_LOAD

    // reduce row sums across the 4 tg lanes of each group
    rs0 += __shfl_xor_sync(0xffffffffu, rs0, 1);
    rs0 += __shfl_xor_sync(0xffffffffu, rs0, 2);
    rs1 += __shfl_xor_sync(0xffffffffu, rs1, 1);
    rs1 += __shfl_xor_sync(0xffffffffu, rs1, 2);
    float inv0 = 1.f / rs0, inv1 = 1.f / rs1;

    // normalize + hardswish + store split-bf16 directly
    int nlo = n0q + 16 * w + g, nhi = nlo + 8;
#pragma unroll
    for (int on = 0; on < 16; on++) {
        int d = h * VDc + 8 * on + 2 * tg;
        if (nlo < Nn) {
            float a0 = o_acc[on][0] * inv0, a1 = o_acc[on][1] * inv0;
            a0 = a0 * fminf(fmaxf(a0 + 3.f, 0.f), 6.f) * (1.f / 6.f);
            a1 = a1 * fminf(fmaxf(a1 + 3.f, 0.f), 6.f) * (1.f / 6.f);
            size_t idx = ((size_t)b * Nn + nlo) * VAL_ATTNc + d;
            __nv_bfloat16 h0 = __float2bfloat16(a0), h1 = __float2bfloat16(a1);
            *(unsigned*)&g_oh[idx] = pk_bf(h0, h1);
            *(unsigned*)&g_ol[idx] = pk_f2(a0 - __bfloat162float(h0), a1 - __bfloat162float(h1));
        }
        if (nhi < Nn) {
            float a2 = o_acc[on][2] * inv1, a3 = o_acc[on][3] * inv1;
            a2 = a2 * fminf(fmaxf(a2 + 3.f, 0.f), 6.f) * (1.f / 6.f);
            a3 = a3 * fminf(fmaxf(a3 + 3.f, 0.f), 6.f) * (1.f / 6.f);
            size_t idx = ((size_t)b * Nn + nhi) * VAL_ATTNc + d;
            __nv_bfloat16 h2 = __float2bfloat16(a2), h3 = __float2bfloat16(a3);
            *(unsigned*)&g_oh[idx] = pk_bf(h2, h3);
            *(unsigned*)&g_ol[idx] = pk_f2(a2 - __bfloat162float(h2), a3 - __bfloat162float(h3));
        }
    }
}

// ---------------- launch ----------------
extern "C" void kernel_launch(void* const* d_in, const int* in_sizes, int n_in,
                              void* d_out, int out_size) {
    (void)in_sizes; (void)n_in; (void)out_size;
    const float* x      = (const float*)d_in[0];
    const float* qkv_w  = (const float*)d_in[1];
    const float* qkv_g  = (const float*)d_in[2];
    const float* qkv_b  = (const float*)d_in[3];
    const float* qkv_m  = (const float*)d_in[4];
    const float* qkv_v  = (const float*)d_in[5];
    const float* ab     = (const float*)d_in[6];
    const float* proj_w = (const float*)d_in[7];
    const float* proj_g = (const float*)d_in[8];
    const float* proj_b = (const float*)d_in[9];
    const float* proj_m = (const float*)d_in[10];
    const float* proj_v = (const float*)d_in[11];
    const int*   idxs   = (const int*)d_in[12];
    float* out = (float*)d_out;

    bn_coef_kernel<<<6, 256>>>(qkv_g, qkv_b, qkv_m, qkv_v, proj_g, proj_b, proj_m, proj_v);
    bias_kernel<<<(Nn * Nn + 255) / 256, 256>>>(ab, idxs);

    cvt_hilo_kernel<<<(Bc * Nn * DIMc / 4 + 255) / 256, 256>>>(x, 0, Bc * Nn * DIMc / 4);
    cvt_hilo_kernel<<<(QKV_OUTc * DIMc / 4 + 255) / 256, 256>>>(qkv_w, 1, QKV_OUTc * DIMc / 4);
    cvt_hilo_kernel<<<(DIMc * VAL_ATTNc / 4 + 255) / 256, 256>>>(proj_w, 3, DIMc * VAL_ATTNc / 4);

    cudaFuncSetAttribute(mma_gemm_kernel, cudaFuncAttributeMaxDynamicSharedMemorySize, 2 * GSTG);
    mma_gemm_kernel<<<dim3(196, 12), 256, 2 * GSTG>>>(0, nullptr);   // QKV

    cudaFuncSetAttribute(attn_mma_kernel, cudaFuncAttributeMaxDynamicSharedMemorySize, ATTN_SMEM_B);
    attn_mma_kernel<<<dim3(7, Hh, Bc), 256, ATTN_SMEM_B>>>();

    mma_gemm_kernel<<<dim3(196, 4), 256, 2 * GSTG>>>(1, out);        // proj
}